// round 6
// baseline (speedup 1.0000x reference)
#include <cuda_runtime.h>
#include <cuda_bf16.h>
#include <cstdint>

#define Nn  150000
#define Ee  600000
#define FIN 32
#define Hh  128
#define Gg  2048

// ---------------- scratch (device globals) ----------------------------------
__device__ float g_agg[Nn * Hh];
__device__ float g_h  [Nn * Hh];
__device__ float g_pool[Gg * Hh];
__device__ float g_cnt [Gg];
__device__ float g_hd2 [Gg * Hh];
#define WTOT (4096 + 10 * 16384)
__device__ __align__(256) __nv_bfloat16 g_wth[WTOT];
__device__ __align__(256) __nv_bfloat16 g_wtl[WTOT];

// ---------------- helpers -----------------------------------------------------
__device__ __forceinline__ uint32_t smem_u32(const void* p) {
    uint32_t a;
    asm("{ .reg .u64 t; cvta.to.shared.u64 t, %1; cvt.u32.u64 %0, t; }" : "=r"(a) : "l"(p));
    return a;
}

__device__ __forceinline__ void ldsm4(uint32_t (&r)[4], uint32_t addr) {
    asm volatile("ldmatrix.sync.aligned.m8n8.x4.shared.b16 {%0,%1,%2,%3}, [%4];"
                 : "=r"(r[0]), "=r"(r[1]), "=r"(r[2]), "=r"(r[3]) : "r"(addr));
}

__device__ __forceinline__ void mma16816(float (&c)[4], const uint32_t (&a)[4],
                                         uint32_t b0, uint32_t b1) {
    asm volatile(
        "mma.sync.aligned.m16n8k16.row.col.f32.bf16.bf16.f32 "
        "{%0,%1,%2,%3},{%4,%5,%6,%7},{%8,%9},{%0,%1,%2,%3};"
        : "+f"(c[0]), "+f"(c[1]), "+f"(c[2]), "+f"(c[3])
        : "r"(a[0]), "r"(a[1]), "r"(a[2]), "r"(a[3]), "r"(b0), "r"(b1));
}

__device__ __forceinline__ void split2(float a, float b, uint32_t& hv, uint32_t& lv) {
    __nv_bfloat16 ha = __float2bfloat16(a), hb = __float2bfloat16(b);
    float la = a - __bfloat162float(ha), lb = b - __bfloat162float(hb);
    __nv_bfloat162 hp = __halves2bfloat162(ha, hb);
    __nv_bfloat162 lp = __floats2bfloat162_rn(la, lb);
    hv = *reinterpret_cast<uint32_t*>(&hp);
    lv = *reinterpret_cast<uint32_t*>(&lp);
}

__device__ __forceinline__ void red4(float* p, float4 v) {
    asm volatile("red.global.add.v4.f32 [%0], {%1, %2, %3, %4};"
                 :: "l"(p), "f"(v.x), "f"(v.y), "f"(v.z), "f"(v.w) : "memory");
}

__device__ __forceinline__ void cp16(uint32_t smem_addr, const void* gptr) {
    asm volatile("cp.async.cg.shared.global [%0], [%1], 16;" :: "r"(smem_addr), "l"(gptr));
}
#define CP_COMMIT() asm volatile("cp.async.commit_group;" ::: "memory")
#define CP_WAIT0()  asm volatile("cp.async.wait_group 0;" ::: "memory")

// ---------------- smem layout: A pair (128x136) + 2 B buffers ------------------
#define PITCH 136
#define SM_A_HI 0u
#define SM_A_LO 34816u
#define SM_B0   69632u
#define SM_BBUF 69632u
#define SM_B_HI(buf) (SM_B0 + (uint32_t)(buf) * SM_BBUF)
#define SM_B_LO(buf) (SM_B0 + (uint32_t)(buf) * SM_BBUF + 34816u)
#define SMEM_FUSED 208896

// ---- GEMM stage: acc[2][4][4] += A(warp_m 32 rows) @ B^T(warp_n 32 cols), 3 combos
template<int Ks>
__device__ __forceinline__ void gemm_acc(uint32_t sb, uint32_t bbase,
                                         float (&acc)[2][4][4],
                                         int lane, int warp_m, int warp_n) {
#pragma unroll
    for (int i = 0; i < 2; i++)
#pragma unroll
        for (int j = 0; j < 4; j++)
#pragma unroll
            for (int k = 0; k < 4; k++) acc[i][j][k] = 0.f;

    int a_r = lane & 15;
    int a_c = (lane & 16) ? 8 : 0;
    int b_r = (lane & 7) + ((lane & 16) ? 8 : 0);
    int b_c = (lane & 8) ? 8 : 0;

#pragma unroll
    for (int kk = 0; kk < Ks / 16; kk++) {
        uint32_t ah[2][4], al[2][4], bh[2][4], bl[2][4];
#pragma unroll
        for (int mt = 0; mt < 2; mt++) {
            uint32_t off = (uint32_t)(((warp_m * 32 + mt * 16 + a_r) * PITCH + kk * 16 + a_c) * 2);
            ldsm4(ah[mt], sb + SM_A_HI + off);
            ldsm4(al[mt], sb + SM_A_LO + off);
        }
#pragma unroll
        for (int p = 0; p < 2; p++) {
            uint32_t off = (uint32_t)(((warp_n * 32 + p * 16 + b_r) * PITCH + kk * 16 + b_c) * 2);
            ldsm4(bh[p], sb + bbase + off);
            ldsm4(bl[p], sb + bbase + 34816u + off);
        }
#pragma unroll
        for (int mt = 0; mt < 2; mt++)
#pragma unroll
            for (int nt = 0; nt < 4; nt++) {
                int p = nt >> 1, q = (nt & 1) * 2;
                mma16816(acc[mt][nt], ah[mt], bh[p][q], bh[p][q + 1]);
                mma16816(acc[mt][nt], ah[mt], bl[p][q], bl[p][q + 1]);
                mma16816(acc[mt][nt], al[mt], bh[p][q], bh[p][q + 1]);
            }
    }
}

// ---- relu(acc+bias) -> split pair into A smem tile -----------------------------
__device__ __forceinline__ void stage_to_smem(char* smem, float (&acc)[2][4][4],
                                              const float* __restrict__ bias,
                                              int lane, int warp_m, int warp_n) {
    int qrow = lane >> 2, qcol = (lane & 3) * 2;
#pragma unroll
    for (int mt = 0; mt < 2; mt++) {
        int r0 = warp_m * 32 + mt * 16 + qrow;
#pragma unroll
        for (int nt = 0; nt < 4; nt++) {
            int col = warp_n * 32 + nt * 8 + qcol;
            float bs0 = __ldg(bias + col), bs1 = __ldg(bias + col + 1);
            float o0 = fmaxf(acc[mt][nt][0] + bs0, 0.f);
            float o1 = fmaxf(acc[mt][nt][1] + bs1, 0.f);
            float o2 = fmaxf(acc[mt][nt][2] + bs0, 0.f);
            float o3 = fmaxf(acc[mt][nt][3] + bs1, 0.f);
            uint32_t h0, l0, h1, l1;
            split2(o0, o1, h0, l0);
            split2(o2, o3, h1, l1);
            *reinterpret_cast<uint32_t*>(smem + SM_A_HI + ((size_t)r0 * PITCH + col) * 2) = h0;
            *reinterpret_cast<uint32_t*>(smem + SM_A_LO + ((size_t)r0 * PITCH + col) * 2) = l0;
            *reinterpret_cast<uint32_t*>(smem + SM_A_HI + ((size_t)(r0 + 8) * PITCH + col) * 2) = h1;
            *reinterpret_cast<uint32_t*>(smem + SM_A_LO + ((size_t)(r0 + 8) * PITCH + col) * 2) = l1;
        }
    }
}

// ---- async prefetch weight tile (128 x Kw) into B buffer -----------------------
template<int Kw>
__device__ __forceinline__ void prefetch_w(uint32_t sb, uint32_t b_hi, uint32_t b_lo,
                                           const __nv_bfloat16* __restrict__ wh,
                                           const __nv_bfloat16* __restrict__ wl, int tid) {
    constexpr int CH = Kw / 8;
    constexpr int ITER = 128 * CH / 512;
#pragma unroll
    for (int it = 0; it < ITER; it++) {
        int l = tid + it * 512;
        int row = l / CH, col = (l % CH) * 8;
        uint32_t so = (uint32_t)((row * PITCH + col) * 2);
        cp16(sb + b_hi + so, wh + (size_t)row * Kw + col);
        cp16(sb + b_lo + so, wl + (size_t)row * Kw + col);
    }
}

struct FusedW {
    const __nv_bfloat16* wh[3];
    const __nv_bfloat16* wl[3];
    const float* b[3];
};

// ---------------- fused MLP: NST chained GEMMs, 128-row tile, 512 threads --------
template<int K0, int NST, int IN>
__global__ __launch_bounds__(512, 1)
void fused_mlp(const float* __restrict__ A, const float* __restrict__ A2,
               FusedW fw, float* __restrict__ C, int M) {
    extern __shared__ char smem[];
    uint32_t sb = smem_u32(smem);
    int tid = threadIdx.x, lane = tid & 31, wid = tid >> 5;
    int warp_m = wid & 3, warp_n = wid >> 2;
    int m0 = blockIdx.x * 128;

    // prefetch stage-0 weights
    prefetch_w<K0>(sb, SM_B_HI(0), SM_B_LO(0), fw.wh[0], fw.wl[0], tid);
    CP_COMMIT();

    // load + split A (128 x K0)
    {
        constexpr int CH = K0 / 4;
        constexpr int ITER = 128 * CH / 512;
#pragma unroll
        for (int it = 0; it < ITER; it++) {
            int l = tid + it * 512;
            int row = l / CH, col = (l % CH) * 4;
            float4 v = make_float4(0.f, 0.f, 0.f, 0.f);
            int m = m0 + row;
            if (m < M) {
                v = *reinterpret_cast<const float4*>(A + (size_t)m * K0 + col);
                if (IN == 1) {
                    float4 w = *reinterpret_cast<const float4*>(A2 + (size_t)m * K0 + col);
                    v.x += w.x; v.y += w.y; v.z += w.z; v.w += w.w;
                }
            }
            uint32_t h0, l0, h1, l1;
            split2(v.x, v.y, h0, l0);
            split2(v.z, v.w, h1, l1);
            *reinterpret_cast<uint2*>(smem + SM_A_HI + ((size_t)row * PITCH + col) * 2) = make_uint2(h0, h1);
            *reinterpret_cast<uint2*>(smem + SM_A_LO + ((size_t)row * PITCH + col) * 2) = make_uint2(l0, l1);
        }
    }
    CP_WAIT0();
    __syncthreads();

    float acc[2][4][4];
    // stage 0 (prefetch stage 1 first so it overlaps the MMAs)
    if (NST > 1) {
        prefetch_w<128>(sb, SM_B_HI(1), SM_B_LO(1), fw.wh[1], fw.wl[1], tid);
        CP_COMMIT();
    }
    gemm_acc<K0>(sb, SM_B_HI(0), acc, lane, warp_m, warp_n);

#pragma unroll
    for (int s = 1; s < NST; s++) {
        CP_WAIT0();                 // stage-s weights landed
        __syncthreads();            // all warps done reading A and B[s-1]
        stage_to_smem(smem, acc, fw.b[s - 1], lane, warp_m, warp_n);
        if (s + 1 < NST) {          // prefetch stage s+1 into the buffer freed at stage s-1
            prefetch_w<128>(sb, SM_B_HI((s + 1) & 1), SM_B_LO((s + 1) & 1),
                            fw.wh[s + 1], fw.wl[s + 1], tid);
            CP_COMMIT();
        }
        __syncthreads();
        gemm_acc<128>(sb, SM_B_HI(s & 1), acc, lane, warp_m, warp_n);
    }

    // final epilogue
    const float* bias = fw.b[NST - 1];
    int qrow = lane >> 2, qcol = (lane & 3) * 2;
#pragma unroll
    for (int mt = 0; mt < 2; mt++) {
        int r0 = m0 + warp_m * 32 + mt * 16 + qrow;
        int r1 = r0 + 8;
#pragma unroll
        for (int nt = 0; nt < 4; nt++) {
            int col = warp_n * 32 + nt * 8 + qcol;
            float bs0 = __ldg(bias + col), bs1 = __ldg(bias + col + 1);
            float o0 = fmaxf(acc[mt][nt][0] + bs0, 0.f);
            float o1 = fmaxf(acc[mt][nt][1] + bs1, 0.f);
            float o2 = fmaxf(acc[mt][nt][2] + bs0, 0.f);
            float o3 = fmaxf(acc[mt][nt][3] + bs1, 0.f);
            if (r0 < M) *reinterpret_cast<float2*>(C + (size_t)r0 * 128 + col) = make_float2(o0, o1);
            if (r1 < M) *reinterpret_cast<float2*>(C + (size_t)r1 * 128 + col) = make_float2(o2, o3);
        }
    }
}

// ---------------- weight prep (11 slots, one launch) ---------------------------
struct WP { const float* p[11]; };

__global__ void prep_all(WP wp, __nv_bfloat16* __restrict__ hi, __nv_bfloat16* __restrict__ lo) {
    int slot = blockIdx.x >> 7;
    int n = blockIdx.x & 127;
    int K = (slot == 0) ? FIN : Hh;
    size_t off = (slot == 0) ? 0 : (size_t)4096 + (size_t)(slot - 1) * 16384;
    const float* W = wp.p[slot];
    for (int k = threadIdx.x; k < K; k += blockDim.x) {
        float v = W[k * Hh + n];
        __nv_bfloat16 h = __float2bfloat16(v);
        hi[off + (size_t)n * K + k] = h;
        lo[off + (size_t)n * K + k] = __float2bfloat16(v - __bfloat162float(h));
    }
}

// ---------------- graph ops -----------------------------------------------------
__global__ void zero_k(float4* p, int n4) {
    int i = blockIdx.x * blockDim.x + threadIdx.x;
    if (i < n4) p[i] = make_float4(0.f, 0.f, 0.f, 0.f);
}

template<int K>
__global__ void scatter_k(float* __restrict__ agg, const float* __restrict__ h,
                          const int* __restrict__ ei) {
    const int C = K / 4;
    int idx = blockIdx.x * blockDim.x + threadIdx.x;
    if (idx >= Ee * C) return;
    int e = idx / C;
    int c = idx - e * C;
    int s = ei[e];
    int d = ei[Ee + e];
    float4 v = reinterpret_cast<const float4*>(h)[(size_t)s * C + c];
    red4(agg + (size_t)d * K + c * 4, v);
}

#define PR 16
__global__ void pool_k(const float* __restrict__ h, const int* __restrict__ batch,
                       float* __restrict__ pool) {
    int gw = (blockIdx.x * blockDim.x + threadIdx.x) >> 5;
    int lane = threadIdx.x & 31;
    const int NB = (Nn + PR - 1) / PR;
    if (gw >= NB) return;
    int n0 = gw * PR;
    int n1 = n0 + PR < Nn ? n0 + PR : Nn;
    float4 acc = make_float4(0.f, 0.f, 0.f, 0.f);
    int cur = batch[n0];
    for (int n = n0; n < n1; n++) {
        int g = batch[n];
        if (g != cur) {
            red4(&pool[(size_t)cur * Hh + lane * 4], acc);
            acc = make_float4(0.f, 0.f, 0.f, 0.f);
            cur = g;
        }
        float4 v = *reinterpret_cast<const float4*>(h + (size_t)n * Hh + lane * 4);
        acc.x += v.x; acc.y += v.y; acc.z += v.z; acc.w += v.w;
    }
    red4(&pool[(size_t)cur * Hh + lane * 4], acc);
}

__global__ void cnt_k(const int* __restrict__ batch, float* __restrict__ cnt) {
    int t = blockIdx.x * blockDim.x + threadIdx.x;
    const int R = 32;
    int n0 = t * R;
    if (n0 >= Nn) return;
    int n1 = n0 + R < Nn ? n0 + R : Nn;
    float acc = 0.f;
    int cur = batch[n0];
    for (int n = n0; n < n1; n++) {
        int g = batch[n];
        if (g != cur) { atomicAdd(&cnt[cur], acc); acc = 0.f; cur = g; }
        acc += 1.f;
    }
    atomicAdd(&cnt[cur], acc);
}

__global__ void div_k(float* __restrict__ pool, const float* __restrict__ cnt) {
    int idx = blockIdx.x * blockDim.x + threadIdx.x;
    if (idx >= Gg * Hh) return;
    pool[idx] *= 1.f / fmaxf(cnt[idx >> 7], 1.f);
}

__global__ void out_k(const float* __restrict__ g2, const float* __restrict__ ow,
                      const float* __restrict__ ob, float* __restrict__ out) {
    int g = blockIdx.x * blockDim.x + threadIdx.x;
    if (g >= Gg) return;
    float s0 = ob[0], s1 = ob[1];
#pragma unroll 4
    for (int k = 0; k < Hh; k++) {
        float v = g2[g * Hh + k];
        s0 += v * ow[k * 2 + 0];
        s1 += v * ow[k * 2 + 1];
    }
    out[g * 2 + 0] = s0;
    out[g * 2 + 1] = s1;
}

// ---------------- launch ----------------------------------------------------------
extern "C" void kernel_launch(void* const* d_in, const int* in_sizes, int n_in,
                              void* d_out, int out_size) {
    const float* x     = (const float*)d_in[0];
    const int*   ei    = (const int*)  d_in[1];
    const int*   batch = (const int*)  d_in[2];
    const float* b1[3], *b2[3], *b3[3];
    WP wp;
    for (int L = 0; L < 3; L++) {
        wp.p[3 * L + 0] = (const float*)d_in[3 + 6 * L + 0];
        b1[L]           = (const float*)d_in[3 + 6 * L + 1];
        wp.p[3 * L + 1] = (const float*)d_in[3 + 6 * L + 2];
        b2[L]           = (const float*)d_in[3 + 6 * L + 3];
        wp.p[3 * L + 2] = (const float*)d_in[3 + 6 * L + 4];
        b3[L]           = (const float*)d_in[3 + 6 * L + 5];
    }
    wp.p[9]  = (const float*)d_in[21];
    const float* fc0b = (const float*)d_in[22];
    wp.p[10] = (const float*)d_in[23];
    const float* fc1b = (const float*)d_in[24];
    const float* outw = (const float*)d_in[25];
    const float* outb = (const float*)d_in[26];

    float *agg, *h, *pool, *cnt, *hd2;
    __nv_bfloat16 *wth, *wtl;
    cudaGetSymbolAddress((void**)&agg,  g_agg);
    cudaGetSymbolAddress((void**)&h,    g_h);
    cudaGetSymbolAddress((void**)&pool, g_pool);
    cudaGetSymbolAddress((void**)&cnt,  g_cnt);
    cudaGetSymbolAddress((void**)&hd2,  g_hd2);
    cudaGetSymbolAddress((void**)&wth,  g_wth);
    cudaGetSymbolAddress((void**)&wtl,  g_wtl);

    auto woff = [](int s) -> size_t { return s == 0 ? 0 : (size_t)4096 + (size_t)(s - 1) * 16384; };

    cudaFuncSetAttribute(fused_mlp<FIN, 3, 1>, cudaFuncAttributeMaxDynamicSharedMemorySize, SMEM_FUSED);
    cudaFuncSetAttribute(fused_mlp<Hh, 3, 1>,  cudaFuncAttributeMaxDynamicSharedMemorySize, SMEM_FUSED);
    cudaFuncSetAttribute(fused_mlp<Hh, 2, 0>,  cudaFuncAttributeMaxDynamicSharedMemorySize, SMEM_FUSED);

    const int TB = 256;
    int ggrid = (Nn + 127) / 128;   // 1172
    int hgrid = (Gg + 127) / 128;   // 16

    prep_all<<<11 * 128, 128>>>(wp, wth, wtl);

    for (int L = 0; L < 3; L++) {
        FusedW fw;
        for (int s = 0; s < 3; s++) {
            fw.wh[s] = wth + woff(3 * L + s);
            fw.wl[s] = wtl + woff(3 * L + s);
        }
        fw.b[0] = b1[L]; fw.b[1] = b2[L]; fw.b[2] = b3[L];

        if (L == 0) {
            zero_k<<<(Nn * FIN / 4 + TB - 1) / TB, TB>>>((float4*)agg, Nn * FIN / 4);
            scatter_k<FIN><<<(Ee * (FIN / 4) + TB - 1) / TB, TB>>>(agg, x, ei);
            fused_mlp<FIN, 3, 1><<<ggrid, 512, SMEM_FUSED>>>(agg, x, fw, h, Nn);
        } else {
            zero_k<<<(Nn * Hh / 4 + TB - 1) / TB, TB>>>((float4*)agg, Nn * Hh / 4);
            scatter_k<Hh><<<(Ee * (Hh / 4) + TB - 1) / TB, TB>>>(agg, h, ei);
            fused_mlp<Hh, 3, 1><<<ggrid, 512, SMEM_FUSED>>>(agg, h, fw, h, Nn);
        }
    }

    // ---- global mean pool ----
    zero_k<<<(Gg * Hh / 4 + TB - 1) / TB, TB>>>((float4*)pool, Gg * Hh / 4);
    zero_k<<<(Gg / 4 + TB - 1) / TB, TB>>>((float4*)cnt, Gg / 4);
    {
        int warps = (Nn + PR - 1) / PR;
        pool_k<<<(warps * 32 + TB - 1) / TB, TB>>>(h, batch, pool);
    }
    cnt_k<<<((Nn + 31) / 32 + TB - 1) / TB, TB>>>(batch, cnt);
    div_k<<<(Gg * Hh + TB - 1) / TB, TB>>>(pool, cnt);

    // ---- classifier head (fc0 + fc1 fused) ----
    {
        FusedW fw;
        fw.wh[0] = wth + woff(9);  fw.wl[0] = wtl + woff(9);
        fw.wh[1] = wth + woff(10); fw.wl[1] = wtl + woff(10);
        fw.wh[2] = nullptr;        fw.wl[2] = nullptr;
        fw.b[0] = fc0b; fw.b[1] = fc1b; fw.b[2] = nullptr;
        fused_mlp<Hh, 2, 0><<<hgrid, 512, SMEM_FUSED>>>(pool, nullptr, fw, hd2, Gg);
    }
    out_k<<<(Gg + 127) / 128, 128>>>(hd2, outw, outb, (float*)d_out);
}

// round 7
// speedup vs baseline: 1.0130x; 1.0130x over previous
#include <cuda_runtime.h>
#include <cuda_bf16.h>
#include <cstdint>

#define Nn  150000
#define Ee  600000
#define FIN 32
#define Hh  128
#define Gg  2048

// ---------------- scratch (device globals) ----------------------------------
__device__ float g_agg [Nn * Hh];
__device__ float g_agg2[Nn * Hh];
__device__ float g_h  [Nn * Hh];
__device__ float g_pool[Gg * Hh];
__device__ float g_cnt [Gg];
__device__ float g_hd2 [Gg * Hh];
#define WTOT (4096 + 10 * 16384)
__device__ __align__(256) __nv_bfloat16 g_wth[WTOT];
__device__ __align__(256) __nv_bfloat16 g_wtl[WTOT];

// ---------------- helpers -----------------------------------------------------
__device__ __forceinline__ uint32_t smem_u32(const void* p) {
    uint32_t a;
    asm("{ .reg .u64 t; cvta.to.shared.u64 t, %1; cvt.u32.u64 %0, t; }" : "=r"(a) : "l"(p));
    return a;
}

__device__ __forceinline__ void ldsm4(uint32_t (&r)[4], uint32_t addr) {
    asm volatile("ldmatrix.sync.aligned.m8n8.x4.shared.b16 {%0,%1,%2,%3}, [%4];"
                 : "=r"(r[0]), "=r"(r[1]), "=r"(r[2]), "=r"(r[3]) : "r"(addr));
}

__device__ __forceinline__ void mma16816(float (&c)[4], const uint32_t (&a)[4],
                                         uint32_t b0, uint32_t b1) {
    asm volatile(
        "mma.sync.aligned.m16n8k16.row.col.f32.bf16.bf16.f32 "
        "{%0,%1,%2,%3},{%4,%5,%6,%7},{%8,%9},{%0,%1,%2,%3};"
        : "+f"(c[0]), "+f"(c[1]), "+f"(c[2]), "+f"(c[3])
        : "r"(a[0]), "r"(a[1]), "r"(a[2]), "r"(a[3]), "r"(b0), "r"(b1));
}

__device__ __forceinline__ void split2(float a, float b, uint32_t& hv, uint32_t& lv) {
    __nv_bfloat16 ha = __float2bfloat16(a), hb = __float2bfloat16(b);
    float la = a - __bfloat162float(ha), lb = b - __bfloat162float(hb);
    __nv_bfloat162 hp = __halves2bfloat162(ha, hb);
    __nv_bfloat162 lp = __floats2bfloat162_rn(la, lb);
    hv = *reinterpret_cast<uint32_t*>(&hp);
    lv = *reinterpret_cast<uint32_t*>(&lp);
}

__device__ __forceinline__ void red4(float* p, float4 v) {
    asm volatile("red.global.add.v4.f32 [%0], {%1, %2, %3, %4};"
                 :: "l"(p), "f"(v.x), "f"(v.y), "f"(v.z), "f"(v.w) : "memory");
}

// ---------------- smem layout: 64-row A pair + 128-row B pair ------------------
#define PITCH 136
#define SM_A_HI 0u
#define SM_A_LO 17408u
#define SM_B_HI 34816u
#define SM_B_LO 69632u
#define SMEM_FUSED 104448

// ---- GEMM stage: warp = 64 rows x 32 cols; acc[4][4][4]; 3 split terms --------
template<int Ks>
__device__ __forceinline__ void gemm_acc(uint32_t sb, float (&acc)[4][4][4],
                                         int lane, int warp_n) {
#pragma unroll
    for (int i = 0; i < 4; i++)
#pragma unroll
        for (int j = 0; j < 4; j++)
#pragma unroll
            for (int k = 0; k < 4; k++) acc[i][j][k] = 0.f;

    int a_r = lane & 15;
    int a_c = (lane & 16) ? 8 : 0;
    int b_r = (lane & 7) + ((lane & 16) ? 8 : 0);
    int b_c = (lane & 8) ? 8 : 0;

#pragma unroll
    for (int kk = 0; kk < Ks / 16; kk++) {
        uint32_t ah[4][4], al[4][4], bh[2][4], bl[2][4];
#pragma unroll
        for (int mt = 0; mt < 4; mt++) {
            uint32_t off = (uint32_t)(((mt * 16 + a_r) * PITCH + kk * 16 + a_c) * 2);
            ldsm4(ah[mt], sb + SM_A_HI + off);
            ldsm4(al[mt], sb + SM_A_LO + off);
        }
#pragma unroll
        for (int p = 0; p < 2; p++) {
            uint32_t off = (uint32_t)(((warp_n * 32 + p * 16 + b_r) * PITCH + kk * 16 + b_c) * 2);
            ldsm4(bh[p], sb + SM_B_HI + off);
            ldsm4(bl[p], sb + SM_B_LO + off);
        }
#pragma unroll
        for (int mt = 0; mt < 4; mt++)
#pragma unroll
            for (int nt = 0; nt < 4; nt++) {
                int p = nt >> 1, q = (nt & 1) * 2;
                mma16816(acc[mt][nt], ah[mt], bh[p][q], bh[p][q + 1]);
                mma16816(acc[mt][nt], ah[mt], bl[p][q], bl[p][q + 1]);
                mma16816(acc[mt][nt], al[mt], bh[p][q], bh[p][q + 1]);
            }
    }
}

// ---- relu(acc+bias) -> split pair into A smem tile -----------------------------
__device__ __forceinline__ void stage_to_smem(char* smem, float (&acc)[4][4][4],
                                              const float* __restrict__ bias,
                                              int lane, int warp_n) {
    int qrow = lane >> 2, qcol = (lane & 3) * 2;
#pragma unroll
    for (int mt = 0; mt < 4; mt++) {
        int r0 = mt * 16 + qrow;
#pragma unroll
        for (int nt = 0; nt < 4; nt++) {
            int col = warp_n * 32 + nt * 8 + qcol;
            float bs0 = __ldg(bias + col), bs1 = __ldg(bias + col + 1);
            float o0 = fmaxf(acc[mt][nt][0] + bs0, 0.f);
            float o1 = fmaxf(acc[mt][nt][1] + bs1, 0.f);
            float o2 = fmaxf(acc[mt][nt][2] + bs0, 0.f);
            float o3 = fmaxf(acc[mt][nt][3] + bs1, 0.f);
            uint32_t h0, l0, h1, l1;
            split2(o0, o1, h0, l0);
            split2(o2, o3, h1, l1);
            *reinterpret_cast<uint32_t*>(smem + SM_A_HI + ((size_t)r0 * PITCH + col) * 2) = h0;
            *reinterpret_cast<uint32_t*>(smem + SM_A_LO + ((size_t)r0 * PITCH + col) * 2) = l0;
            *reinterpret_cast<uint32_t*>(smem + SM_A_HI + ((size_t)(r0 + 8) * PITCH + col) * 2) = h1;
            *reinterpret_cast<uint32_t*>(smem + SM_A_LO + ((size_t)(r0 + 8) * PITCH + col) * 2) = l1;
        }
    }
}

// ---- load weight tile (128 x Kw) into B smem (128 threads) ---------------------
template<int Kw>
__device__ __forceinline__ void load_w(char* smem, const __nv_bfloat16* __restrict__ wh,
                                       const __nv_bfloat16* __restrict__ wl, int tid) {
    constexpr int CH = Kw / 8;
    constexpr int ITER = 128 * CH / 128;
#pragma unroll
    for (int it = 0; it < ITER; it++) {
        int l = tid + it * 128;
        int row = l / CH, col = (l % CH) * 8;
        *reinterpret_cast<uint4*>(smem + SM_B_HI + ((size_t)row * PITCH + col) * 2) =
            *reinterpret_cast<const uint4*>(wh + (size_t)row * Kw + col);
        *reinterpret_cast<uint4*>(smem + SM_B_LO + ((size_t)row * PITCH + col) * 2) =
            *reinterpret_cast<const uint4*>(wl + (size_t)row * Kw + col);
    }
}

struct FusedW {
    const __nv_bfloat16* wh[3];
    const __nv_bfloat16* wl[3];
    const float* b[3];
};

// ---------------- fused MLP: NST chained GEMMs, 64-row tile, 128 threads --------
// IN: 0 = A fp32; 1 = A + A2 fp32. ZAGG: zero Z rows [m0,m0+64) x128 (next agg)
template<int K0, int NST, int IN, int ZAGG>
__global__ __launch_bounds__(128, 2)
void fused_mlp(const float* __restrict__ A, const float* __restrict__ A2,
               FusedW fw, float* __restrict__ C, float* __restrict__ Z, int M) {
    extern __shared__ char smem[];
    uint32_t sb = smem_u32(smem);
    int tid = threadIdx.x, lane = tid & 31, warp_n = tid >> 5;
    int m0 = blockIdx.x * 64;

    // ---- load + split A (64 x K0) ----
    {
        constexpr int CH = K0 / 4;
        constexpr int ITER = 64 * CH / 128;
#pragma unroll
        for (int it = 0; it < ITER; it++) {
            int l = tid + it * 128;
            int row = l / CH, col = (l % CH) * 4;
            float4 v = make_float4(0.f, 0.f, 0.f, 0.f);
            int m = m0 + row;
            if (m < M) {
                v = *reinterpret_cast<const float4*>(A + (size_t)m * K0 + col);
                if (IN == 1) {
                    float4 w = *reinterpret_cast<const float4*>(A2 + (size_t)m * K0 + col);
                    v.x += w.x; v.y += w.y; v.z += w.z; v.w += w.w;
                }
            }
            uint32_t h0, l0, h1, l1;
            split2(v.x, v.y, h0, l0);
            split2(v.z, v.w, h1, l1);
            *reinterpret_cast<uint2*>(smem + SM_A_HI + ((size_t)row * PITCH + col) * 2) = make_uint2(h0, h1);
            *reinterpret_cast<uint2*>(smem + SM_A_LO + ((size_t)row * PITCH + col) * 2) = make_uint2(l0, l1);
        }
    }
    load_w<K0>(smem, fw.wh[0], fw.wl[0], tid);
    __syncthreads();

    // ---- zero next-layer agg rows (hidden under MMA below) ----
    if (ZAGG) {
        const float4 z4 = make_float4(0.f, 0.f, 0.f, 0.f);
#pragma unroll
        for (int it = 0; it < 16; it++) {
            int i = tid + it * 128;          // float4 index within 64x128 slice
            int row = m0 + (i >> 5);
            if (row < M) reinterpret_cast<float4*>(Z + (size_t)row * 128)[i & 31] = z4;
        }
    }

    float acc[4][4][4];
    gemm_acc<K0>(sb, acc, lane, warp_n);

#pragma unroll
    for (int s = 1; s < NST; s++) {
        __syncthreads();
        stage_to_smem(smem, acc, fw.b[s - 1], lane, warp_n);
        load_w<128>(smem, fw.wh[s], fw.wl[s], tid);
        __syncthreads();
        gemm_acc<128>(sb, acc, lane, warp_n);
    }

    // ---- final epilogue ----
    const float* bias = fw.b[NST - 1];
    int qrow = lane >> 2, qcol = (lane & 3) * 2;
#pragma unroll
    for (int mt = 0; mt < 4; mt++) {
        int r0 = m0 + mt * 16 + qrow;
        int r1 = r0 + 8;
#pragma unroll
        for (int nt = 0; nt < 4; nt++) {
            int col = warp_n * 32 + nt * 8 + qcol;
            float bs0 = __ldg(bias + col), bs1 = __ldg(bias + col + 1);
            float o0 = fmaxf(acc[mt][nt][0] + bs0, 0.f);
            float o1 = fmaxf(acc[mt][nt][1] + bs1, 0.f);
            float o2 = fmaxf(acc[mt][nt][2] + bs0, 0.f);
            float o3 = fmaxf(acc[mt][nt][3] + bs1, 0.f);
            if (r0 < M) *reinterpret_cast<float2*>(C + (size_t)r0 * 128 + col) = make_float2(o0, o1);
            if (r1 < M) *reinterpret_cast<float2*>(C + (size_t)r1 * 128 + col) = make_float2(o2, o3);
        }
    }
}

// ---------------- weight prep (11 slots, one launch) ---------------------------
struct WP { const float* p[11]; };

__global__ void prep_all(WP wp, __nv_bfloat16* __restrict__ hi, __nv_bfloat16* __restrict__ lo) {
    int slot = blockIdx.x >> 7;
    int n = blockIdx.x & 127;
    int K = (slot == 0) ? FIN : Hh;
    size_t off = (slot == 0) ? 0 : (size_t)4096 + (size_t)(slot - 1) * 16384;
    const float* W = wp.p[slot];
    for (int k = threadIdx.x; k < K; k += blockDim.x) {
        float v = W[k * Hh + n];
        __nv_bfloat16 h = __float2bfloat16(v);
        hi[off + (size_t)n * K + k] = h;
        lo[off + (size_t)n * K + k] = __float2bfloat16(v - __bfloat162float(h));
    }
}

// ---------------- graph ops -----------------------------------------------------
__global__ void zero_k(float4* p, int n4) {
    int i = blockIdx.x * blockDim.x + threadIdx.x;
    if (i < n4) p[i] = make_float4(0.f, 0.f, 0.f, 0.f);
}

template<int K>
__global__ void scatter_k(float* __restrict__ agg, const float* __restrict__ h,
                          const int* __restrict__ ei) {
    const int C = K / 4;
    int idx = blockIdx.x * blockDim.x + threadIdx.x;
    if (idx >= Ee * C) return;
    int e = idx / C;
    int c = idx - e * C;
    int s = ei[e];
    int d = ei[Ee + e];
    float4 v = reinterpret_cast<const float4*>(h)[(size_t)s * C + c];
    red4(agg + (size_t)d * K + c * 4, v);
}

#define PR 16
__global__ void pool_k(const float* __restrict__ h, const int* __restrict__ batch,
                       float* __restrict__ pool) {
    int gw = (blockIdx.x * blockDim.x + threadIdx.x) >> 5;
    int lane = threadIdx.x & 31;
    const int NB = (Nn + PR - 1) / PR;
    if (gw >= NB) return;
    int n0 = gw * PR;
    int n1 = n0 + PR < Nn ? n0 + PR : Nn;
    float4 acc = make_float4(0.f, 0.f, 0.f, 0.f);
    int cur = batch[n0];
    for (int n = n0; n < n1; n++) {
        int g = batch[n];
        if (g != cur) {
            red4(&pool[(size_t)cur * Hh + lane * 4], acc);
            acc = make_float4(0.f, 0.f, 0.f, 0.f);
            cur = g;
        }
        float4 v = *reinterpret_cast<const float4*>(h + (size_t)n * Hh + lane * 4);
        acc.x += v.x; acc.y += v.y; acc.z += v.z; acc.w += v.w;
    }
    red4(&pool[(size_t)cur * Hh + lane * 4], acc);
}

__global__ void cnt_k(const int* __restrict__ batch, float* __restrict__ cnt) {
    int t = blockIdx.x * blockDim.x + threadIdx.x;
    const int R = 32;
    int n0 = t * R;
    if (n0 >= Nn) return;
    int n1 = n0 + R < Nn ? n0 + R : Nn;
    float acc = 0.f;
    int cur = batch[n0];
    for (int n = n0; n < n1; n++) {
        int g = batch[n];
        if (g != cur) { atomicAdd(&cnt[cur], acc); acc = 0.f; cur = g; }
        acc += 1.f;
    }
    atomicAdd(&cnt[cur], acc);
}

__global__ void div_k(float* __restrict__ pool, const float* __restrict__ cnt) {
    int idx = blockIdx.x * blockDim.x + threadIdx.x;
    if (idx >= Gg * Hh) return;
    pool[idx] *= 1.f / fmaxf(cnt[idx >> 7], 1.f);
}

__global__ void out_k(const float* __restrict__ g2, const float* __restrict__ ow,
                      const float* __restrict__ ob, float* __restrict__ out) {
    int g = blockIdx.x * blockDim.x + threadIdx.x;
    if (g >= Gg) return;
    float s0 = ob[0], s1 = ob[1];
#pragma unroll 4
    for (int k = 0; k < Hh; k++) {
        float v = g2[g * Hh + k];
        s0 += v * ow[k * 2 + 0];
        s1 += v * ow[k * 2 + 1];
    }
    out[g * 2 + 0] = s0;
    out[g * 2 + 1] = s1;
}

// ---------------- launch ----------------------------------------------------------
extern "C" void kernel_launch(void* const* d_in, const int* in_sizes, int n_in,
                              void* d_out, int out_size) {
    const float* x     = (const float*)d_in[0];
    const int*   ei    = (const int*)  d_in[1];
    const int*   batch = (const int*)  d_in[2];
    const float* b1[3], *b2[3], *b3[3];
    WP wp;
    for (int L = 0; L < 3; L++) {
        wp.p[3 * L + 0] = (const float*)d_in[3 + 6 * L + 0];
        b1[L]           = (const float*)d_in[3 + 6 * L + 1];
        wp.p[3 * L + 1] = (const float*)d_in[3 + 6 * L + 2];
        b2[L]           = (const float*)d_in[3 + 6 * L + 3];
        wp.p[3 * L + 2] = (const float*)d_in[3 + 6 * L + 4];
        b3[L]           = (const float*)d_in[3 + 6 * L + 5];
    }
    wp.p[9]  = (const float*)d_in[21];
    const float* fc0b = (const float*)d_in[22];
    wp.p[10] = (const float*)d_in[23];
    const float* fc1b = (const float*)d_in[24];
    const float* outw = (const float*)d_in[25];
    const float* outb = (const float*)d_in[26];

    float *agg, *agg2, *h, *pool, *cnt, *hd2;
    __nv_bfloat16 *wth, *wtl;
    cudaGetSymbolAddress((void**)&agg,  g_agg);
    cudaGetSymbolAddress((void**)&agg2, g_agg2);
    cudaGetSymbolAddress((void**)&h,    g_h);
    cudaGetSymbolAddress((void**)&pool, g_pool);
    cudaGetSymbolAddress((void**)&cnt,  g_cnt);
    cudaGetSymbolAddress((void**)&hd2,  g_hd2);
    cudaGetSymbolAddress((void**)&wth,  g_wth);
    cudaGetSymbolAddress((void**)&wtl,  g_wtl);

    auto woff = [](int s) -> size_t { return s == 0 ? 0 : (size_t)4096 + (size_t)(s - 1) * 16384; };

    cudaFuncSetAttribute(fused_mlp<FIN, 3, 1, 1>, cudaFuncAttributeMaxDynamicSharedMemorySize, SMEM_FUSED);
    cudaFuncSetAttribute(fused_mlp<Hh, 3, 1, 1>,  cudaFuncAttributeMaxDynamicSharedMemorySize, SMEM_FUSED);
    cudaFuncSetAttribute(fused_mlp<Hh, 3, 1, 0>,  cudaFuncAttributeMaxDynamicSharedMemorySize, SMEM_FUSED);
    cudaFuncSetAttribute(fused_mlp<Hh, 2, 0, 0>,  cudaFuncAttributeMaxDynamicSharedMemorySize, SMEM_FUSED);

    const int TB = 256;
    int ggrid = (Nn + 63) / 64;   // 2344
    int hgrid = (Gg + 63) / 64;   // 32

    prep_all<<<11 * 128, 128>>>(wp, wth, wtl);

    // ---- layer 0 (K0 = 32): agg (32-col) zero + scatter; MLP zeros agg2 ----
    zero_k<<<(Nn * FIN / 4 + TB - 1) / TB, TB>>>((float4*)agg, Nn * FIN / 4);
    scatter_k<FIN><<<(Ee * (FIN / 4) + TB - 1) / TB, TB>>>(agg, x, ei);
    {
        FusedW fw;
        for (int s = 0; s < 3; s++) { fw.wh[s] = wth + woff(s); fw.wl[s] = wtl + woff(s); }
        fw.b[0] = b1[0]; fw.b[1] = b2[0]; fw.b[2] = b3[0];
        fused_mlp<FIN, 3, 1, 1><<<ggrid, 128, SMEM_FUSED>>>(agg, x, fw, h, agg2, Nn);
    }

    // ---- layer 1: scatter into agg2 (zeroed by L0); MLP zeros agg ----
    scatter_k<Hh><<<(Ee * (Hh / 4) + TB - 1) / TB, TB>>>(agg2, h, ei);
    {
        FusedW fw;
        for (int s = 0; s < 3; s++) { fw.wh[s] = wth + woff(3 + s); fw.wl[s] = wtl + woff(3 + s); }
        fw.b[0] = b1[1]; fw.b[1] = b2[1]; fw.b[2] = b3[1];
        fused_mlp<Hh, 3, 1, 1><<<ggrid, 128, SMEM_FUSED>>>(agg2, h, fw, h, agg, Nn);
    }

    // ---- layer 2: scatter into agg (zeroed by L1); no further agg needed ----
    scatter_k<Hh><<<(Ee * (Hh / 4) + TB - 1) / TB, TB>>>(agg, h, ei);
    {
        FusedW fw;
        for (int s = 0; s < 3; s++) { fw.wh[s] = wth + woff(6 + s); fw.wl[s] = wtl + woff(6 + s); }
        fw.b[0] = b1[2]; fw.b[1] = b2[2]; fw.b[2] = b3[2];
        fused_mlp<Hh, 3, 1, 0><<<ggrid, 128, SMEM_FUSED>>>(agg, h, fw, h, nullptr, Nn);
    }

    // ---- global mean pool ----
    zero_k<<<(Gg * Hh / 4 + TB - 1) / TB, TB>>>((float4*)pool, Gg * Hh / 4);
    zero_k<<<(Gg / 4 + TB - 1) / TB, TB>>>((float4*)cnt, Gg / 4);
    {
        int warps = (Nn + PR - 1) / PR;
        pool_k<<<(warps * 32 + TB - 1) / TB, TB>>>(h, batch, pool);
    }
    cnt_k<<<((Nn + 31) / 32 + TB - 1) / TB, TB>>>(batch, cnt);
    div_k<<<(Gg * Hh + TB - 1) / TB, TB>>>(pool, cnt);

    // ---- classifier head (fc0 + fc1 fused) ----
    {
        FusedW fw;
        fw.wh[0] = wth + woff(9);  fw.wl[0] = wtl + woff(9);
        fw.wh[1] = wth + woff(10); fw.wl[1] = wtl + woff(10);
        fw.wh[2] = nullptr;        fw.wl[2] = nullptr;
        fw.b[0] = fc0b; fw.b[1] = fc1b; fw.b[2] = nullptr;
        fused_mlp<Hh, 2, 0, 0><<<hgrid, 128, SMEM_FUSED>>>(pool, nullptr, fw, hd2, nullptr, Gg);
    }
    out_k<<<(Gg + 127) / 128, 128>>>(hd2, outw, outb, (float*)d_out);
}

// round 8
// speedup vs baseline: 1.0400x; 1.0266x over previous
#include <cuda_runtime.h>
#include <cuda_bf16.h>
#include <cstdint>

#define Nn  150000
#define Ee  600000
#define FIN 32
#define Hh  128
#define Gg  2048

// ---------------- scratch (device globals) ----------------------------------
__device__ float g_agg [Nn * Hh];
__device__ float g_agg2[Nn * Hh];
__device__ float g_h  [Nn * Hh];
__device__ float g_pool[Gg * Hh];
__device__ float g_cnt [Gg];
__device__ float g_hd2 [Gg * Hh];
#define WTOT (4096 + 10 * 16384)
__device__ __align__(256) __nv_bfloat16 g_wth[WTOT];
__device__ __align__(256) __nv_bfloat16 g_wtl[WTOT];

// ---------------- helpers -----------------------------------------------------
__device__ __forceinline__ uint32_t smem_u32(const void* p) {
    uint32_t a;
    asm("{ .reg .u64 t; cvta.to.shared.u64 t, %1; cvt.u32.u64 %0, t; }" : "=r"(a) : "l"(p));
    return a;
}

__device__ __forceinline__ void ldsm4(uint32_t (&r)[4], uint32_t addr) {
    asm volatile("ldmatrix.sync.aligned.m8n8.x4.shared.b16 {%0,%1,%2,%3}, [%4];"
                 : "=r"(r[0]), "=r"(r[1]), "=r"(r[2]), "=r"(r[3]) : "r"(addr));
}

__device__ __forceinline__ void mma16816(float (&c)[4], const uint32_t (&a)[4],
                                         uint32_t b0, uint32_t b1) {
    asm volatile(
        "mma.sync.aligned.m16n8k16.row.col.f32.bf16.bf16.f32 "
        "{%0,%1,%2,%3},{%4,%5,%6,%7},{%8,%9},{%0,%1,%2,%3};"
        : "+f"(c[0]), "+f"(c[1]), "+f"(c[2]), "+f"(c[3])
        : "r"(a[0]), "r"(a[1]), "r"(a[2]), "r"(a[3]), "r"(b0), "r"(b1));
}

__device__ __forceinline__ void split2(float a, float b, uint32_t& hv, uint32_t& lv) {
    __nv_bfloat16 ha = __float2bfloat16(a), hb = __float2bfloat16(b);
    float la = a - __bfloat162float(ha), lb = b - __bfloat162float(hb);
    __nv_bfloat162 hp = __halves2bfloat162(ha, hb);
    __nv_bfloat162 lp = __floats2bfloat162_rn(la, lb);
    hv = *reinterpret_cast<uint32_t*>(&hp);
    lv = *reinterpret_cast<uint32_t*>(&lp);
}

__device__ __forceinline__ void red4(float* p, float4 v) {
    asm volatile("red.global.add.v4.f32 [%0], {%1, %2, %3, %4};"
                 :: "l"(p), "f"(v.x), "f"(v.y), "f"(v.z), "f"(v.w) : "memory");
}

// ---------------- smem layout (round-5 proven config) ---------------------------
#define PITCH 136
#define OFF_A_HI 0u
#define OFF_A_LO 17408u
#define OFF_B_HI 34816u
#define OFF_B_LO 69632u
#define SMEM_FUSED 104448

// ---- GEMM stage: warp = 32 rows x 32 cols; acc[2][4][4]; 3 split terms --------
template<int Ks>
__device__ __forceinline__ void gemm_acc(uint32_t sb, float (&acc)[2][4][4],
                                         int lane, int warp_m, int warp_n) {
#pragma unroll
    for (int i = 0; i < 2; i++)
#pragma unroll
        for (int j = 0; j < 4; j++)
#pragma unroll
            for (int k = 0; k < 4; k++) acc[i][j][k] = 0.f;

    int a_r = lane & 15;
    int a_c = (lane & 16) ? 8 : 0;
    int b_r = (lane & 7) + ((lane & 16) ? 8 : 0);
    int b_c = (lane & 8) ? 8 : 0;

#pragma unroll
    for (int kk = 0; kk < Ks / 16; kk++) {
        uint32_t ah[2][4], al[2][4], bh[2][4], bl[2][4];
#pragma unroll
        for (int mt = 0; mt < 2; mt++) {
            uint32_t off = (uint32_t)(((warp_m * 32 + mt * 16 + a_r) * PITCH + kk * 16 + a_c) * 2);
            ldsm4(ah[mt], sb + OFF_A_HI + off);
            ldsm4(al[mt], sb + OFF_A_LO + off);
        }
#pragma unroll
        for (int p = 0; p < 2; p++) {
            uint32_t off = (uint32_t)(((warp_n * 32 + p * 16 + b_r) * PITCH + kk * 16 + b_c) * 2);
            ldsm4(bh[p], sb + OFF_B_HI + off);
            ldsm4(bl[p], sb + OFF_B_LO + off);
        }
#pragma unroll
        for (int mt = 0; mt < 2; mt++)
#pragma unroll
            for (int nt = 0; nt < 4; nt++) {
                int p = nt >> 1, q = (nt & 1) * 2;
                mma16816(acc[mt][nt], ah[mt], bh[p][q], bh[p][q + 1]);
                mma16816(acc[mt][nt], ah[mt], bl[p][q], bl[p][q + 1]);
                mma16816(acc[mt][nt], al[mt], bh[p][q], bh[p][q + 1]);
            }
    }
}

__device__ __forceinline__ void stage_to_smem(char* smem, float (&acc)[2][4][4],
                                              const float* __restrict__ bias,
                                              int lane, int warp_m, int warp_n) {
    int qrow = lane >> 2, qcol = (lane & 3) * 2;
#pragma unroll
    for (int mt = 0; mt < 2; mt++) {
        int r0 = warp_m * 32 + mt * 16 + qrow;
#pragma unroll
        for (int nt = 0; nt < 4; nt++) {
            int col = warp_n * 32 + nt * 8 + qcol;
            float bs0 = __ldg(bias + col), bs1 = __ldg(bias + col + 1);
            float o0 = fmaxf(acc[mt][nt][0] + bs0, 0.f);
            float o1 = fmaxf(acc[mt][nt][1] + bs1, 0.f);
            float o2 = fmaxf(acc[mt][nt][2] + bs0, 0.f);
            float o3 = fmaxf(acc[mt][nt][3] + bs1, 0.f);
            uint32_t h0, l0, h1, l1;
            split2(o0, o1, h0, l0);
            split2(o2, o3, h1, l1);
            *reinterpret_cast<uint32_t*>(smem + OFF_A_HI + ((size_t)r0 * PITCH + col) * 2) = h0;
            *reinterpret_cast<uint32_t*>(smem + OFF_A_LO + ((size_t)r0 * PITCH + col) * 2) = l0;
            *reinterpret_cast<uint32_t*>(smem + OFF_A_HI + ((size_t)(r0 + 8) * PITCH + col) * 2) = h1;
            *reinterpret_cast<uint32_t*>(smem + OFF_A_LO + ((size_t)(r0 + 8) * PITCH + col) * 2) = l1;
        }
    }
}

template<int Kw>
__device__ __forceinline__ void load_w(char* smem, const __nv_bfloat16* __restrict__ wh,
                                       const __nv_bfloat16* __restrict__ wl, int tid) {
    constexpr int CH = Kw / 8;
    constexpr int ITER = 128 * CH / 256;
#pragma unroll
    for (int it = 0; it < ITER; it++) {
        int l = tid + it * 256;
        int row = l / CH, col = (l % CH) * 8;
        *reinterpret_cast<uint4*>(smem + OFF_B_HI + ((size_t)row * PITCH + col) * 2) =
            *reinterpret_cast<const uint4*>(wh + (size_t)row * Kw + col);
        *reinterpret_cast<uint4*>(smem + OFF_B_LO + ((size_t)row * PITCH + col) * 2) =
            *reinterpret_cast<const uint4*>(wl + (size_t)row * Kw + col);
    }
}

struct FusedW {
    const __nv_bfloat16* wh[3];
    const __nv_bfloat16* wl[3];
    const float* b[3];
};

// ---------------- fused MLP (round-5 shape) + inline zeroing --------------------
// IN: 0 = A fp32; 1 = A + A2 fp32.
// ZAGG: 0 none; 1 zero Z rows [m0,m0+64)x128; 2 zero pool (Z) + cnt (Zc) slices.
template<int K0, int NST, int IN, int ZAGG>
__global__ __launch_bounds__(256, 2)
void fused_mlp(const float* __restrict__ A, const float* __restrict__ A2,
               FusedW fw, float* __restrict__ C,
               float* __restrict__ Z, float* __restrict__ Zc, int M) {
    extern __shared__ char smem[];
    uint32_t sb = smem_u32(smem);
    int tid = threadIdx.x, lane = tid & 31, wid = tid >> 5;
    int warp_m = wid & 1, warp_n = wid >> 1;
    int m0 = blockIdx.x * 64;

    // ---- load + split A (64 x K0) ----
    {
        constexpr int CH = K0 / 4;
        constexpr int ITER = 64 * CH / 256;
#pragma unroll
        for (int it = 0; it < ITER; it++) {
            int l = tid + it * 256;
            int row = l / CH, col = (l % CH) * 4;
            float4 v = make_float4(0.f, 0.f, 0.f, 0.f);
            int m = m0 + row;
            if (m < M) {
                v = *reinterpret_cast<const float4*>(A + (size_t)m * K0 + col);
                if (IN == 1) {
                    float4 w = *reinterpret_cast<const float4*>(A2 + (size_t)m * K0 + col);
                    v.x += w.x; v.y += w.y; v.z += w.z; v.w += w.w;
                }
            }
            uint32_t h0, l0, h1, l1;
            split2(v.x, v.y, h0, l0);
            split2(v.z, v.w, h1, l1);
            *reinterpret_cast<uint2*>(smem + OFF_A_HI + ((size_t)row * PITCH + col) * 2) = make_uint2(h0, h1);
            *reinterpret_cast<uint2*>(smem + OFF_A_LO + ((size_t)row * PITCH + col) * 2) = make_uint2(l0, l1);
        }
    }
    load_w<K0>(smem, fw.wh[0], fw.wl[0], tid);
    __syncthreads();

    // ---- inline zeroing (fire-and-forget STGs, hidden under the MMAs below) ----
    if (ZAGG == 1) {
        const float4 z4 = make_float4(0.f, 0.f, 0.f, 0.f);
#pragma unroll
        for (int it = 0; it < 8; it++) {
            int i = tid + it * 256;                  // float4 index in 64x128 slice
            int row = m0 + (i >> 5);
            if (row < M) reinterpret_cast<float4*>(Z + (size_t)row * 128)[i & 31] = z4;
        }
    } else if (ZAGG == 2) {
        const float4 z4 = make_float4(0.f, 0.f, 0.f, 0.f);
        if (blockIdx.x < 32) {                        // pool: 2048 rows = 32 blocks x 64 rows
#pragma unroll
            for (int it = 0; it < 8; it++) {
                int i = tid + it * 256;
                int row = (int)blockIdx.x * 64 + (i >> 5);
                reinterpret_cast<float4*>(Z + (size_t)row * 128)[i & 31] = z4;
            }
        } else if (blockIdx.x == 32) {                // cnt: 2048 floats = 512 float4
#pragma unroll
            for (int it = 0; it < 2; it++)
                reinterpret_cast<float4*>(Zc)[tid + it * 256] = z4;
        }
    }

    float acc[2][4][4];
    gemm_acc<K0>(sb, acc, lane, warp_m, warp_n);

#pragma unroll
    for (int s = 1; s < NST; s++) {
        __syncthreads();
        stage_to_smem(smem, acc, fw.b[s - 1], lane, warp_m, warp_n);
        load_w<128>(smem, fw.wh[s], fw.wl[s], tid);
        __syncthreads();
        gemm_acc<128>(sb, acc, lane, warp_m, warp_n);
    }

    const float* bias = fw.b[NST - 1];
    int qrow = lane >> 2, qcol = (lane & 3) * 2;
#pragma unroll
    for (int mt = 0; mt < 2; mt++) {
        int r0 = m0 + warp_m * 32 + mt * 16 + qrow;
        int r1 = r0 + 8;
#pragma unroll
        for (int nt = 0; nt < 4; nt++) {
            int col = warp_n * 32 + nt * 8 + qcol;
            float bs0 = __ldg(bias + col), bs1 = __ldg(bias + col + 1);
            float o0 = fmaxf(acc[mt][nt][0] + bs0, 0.f);
            float o1 = fmaxf(acc[mt][nt][1] + bs1, 0.f);
            float o2 = fmaxf(acc[mt][nt][2] + bs0, 0.f);
            float o3 = fmaxf(acc[mt][nt][3] + bs1, 0.f);
            if (r0 < M) *reinterpret_cast<float2*>(C + (size_t)r0 * 128 + col) = make_float2(o0, o1);
            if (r1 < M) *reinterpret_cast<float2*>(C + (size_t)r1 * 128 + col) = make_float2(o2, o3);
        }
    }
}

// ---------------- weight prep (11 slots, one launch) ---------------------------
struct WP { const float* p[11]; };

__global__ void prep_all(WP wp, __nv_bfloat16* __restrict__ hi, __nv_bfloat16* __restrict__ lo) {
    int slot = blockIdx.x >> 7;
    int n = blockIdx.x & 127;
    int K = (slot == 0) ? FIN : Hh;
    size_t off = (slot == 0) ? 0 : (size_t)4096 + (size_t)(slot - 1) * 16384;
    const float* W = wp.p[slot];
    for (int k = threadIdx.x; k < K; k += blockDim.x) {
        float v = W[k * Hh + n];
        __nv_bfloat16 h = __float2bfloat16(v);
        hi[off + (size_t)n * K + k] = h;
        lo[off + (size_t)n * K + k] = __float2bfloat16(v - __bfloat162float(h));
    }
}

// ---------------- graph ops -----------------------------------------------------
__global__ void zero_k(float4* p, int n4) {
    int i = blockIdx.x * blockDim.x + threadIdx.x;
    if (i < n4) p[i] = make_float4(0.f, 0.f, 0.f, 0.f);
}

template<int K>
__global__ void scatter_k(float* __restrict__ agg, const float* __restrict__ h,
                          const int* __restrict__ ei) {
    const int C = K / 4;
    int idx = blockIdx.x * blockDim.x + threadIdx.x;
    if (idx >= Ee * C) return;
    int e = idx / C;
    int c = idx - e * C;
    int s = ei[e];
    int d = ei[Ee + e];
    float4 v = reinterpret_cast<const float4*>(h)[(size_t)s * C + c];
    red4(agg + (size_t)d * K + c * 4, v);
}

#define PR 16
__global__ void pool_k(const float* __restrict__ h, const int* __restrict__ batch,
                       float* __restrict__ pool) {
    int gw = (blockIdx.x * blockDim.x + threadIdx.x) >> 5;
    int lane = threadIdx.x & 31;
    const int NB = (Nn + PR - 1) / PR;
    if (gw >= NB) return;
    int n0 = gw * PR;
    int n1 = n0 + PR < Nn ? n0 + PR : Nn;
    float4 acc = make_float4(0.f, 0.f, 0.f, 0.f);
    int cur = batch[n0];
    for (int n = n0; n < n1; n++) {
        int g = batch[n];
        if (g != cur) {
            red4(&pool[(size_t)cur * Hh + lane * 4], acc);
            acc = make_float4(0.f, 0.f, 0.f, 0.f);
            cur = g;
        }
        float4 v = *reinterpret_cast<const float4*>(h + (size_t)n * Hh + lane * 4);
        acc.x += v.x; acc.y += v.y; acc.z += v.z; acc.w += v.w;
    }
    red4(&pool[(size_t)cur * Hh + lane * 4], acc);
}

__global__ void cnt_k(const int* __restrict__ batch, float* __restrict__ cnt) {
    int t = blockIdx.x * blockDim.x + threadIdx.x;
    const int R = 32;
    int n0 = t * R;
    if (n0 >= Nn) return;
    int n1 = n0 + R < Nn ? n0 + R : Nn;
    float acc = 0.f;
    int cur = batch[n0];
    for (int n = n0; n < n1; n++) {
        int g = batch[n];
        if (g != cur) { atomicAdd(&cnt[cur], acc); acc = 0.f; cur = g; }
        acc += 1.f;
    }
    atomicAdd(&cnt[cur], acc);
}

__global__ void div_k(float* __restrict__ pool, const float* __restrict__ cnt) {
    int idx = blockIdx.x * blockDim.x + threadIdx.x;
    if (idx >= Gg * Hh) return;
    pool[idx] *= 1.f / fmaxf(cnt[idx >> 7], 1.f);
}

__global__ void out_k(const float* __restrict__ g2, const float* __restrict__ ow,
                      const float* __restrict__ ob, float* __restrict__ out) {
    int g = blockIdx.x * blockDim.x + threadIdx.x;
    if (g >= Gg) return;
    float s0 = ob[0], s1 = ob[1];
#pragma unroll 4
    for (int k = 0; k < Hh; k++) {
        float v = g2[g * Hh + k];
        s0 += v * ow[k * 2 + 0];
        s1 += v * ow[k * 2 + 1];
    }
    out[g * 2 + 0] = s0;
    out[g * 2 + 1] = s1;
}

// ---------------- launch ----------------------------------------------------------
extern "C" void kernel_launch(void* const* d_in, const int* in_sizes, int n_in,
                              void* d_out, int out_size) {
    const float* x     = (const float*)d_in[0];
    const int*   ei    = (const int*)  d_in[1];
    const int*   batch = (const int*)  d_in[2];
    const float* b1[3], *b2[3], *b3[3];
    WP wp;
    for (int L = 0; L < 3; L++) {
        wp.p[3 * L + 0] = (const float*)d_in[3 + 6 * L + 0];
        b1[L]           = (const float*)d_in[3 + 6 * L + 1];
        wp.p[3 * L + 1] = (const float*)d_in[3 + 6 * L + 2];
        b2[L]           = (const float*)d_in[3 + 6 * L + 3];
        wp.p[3 * L + 2] = (const float*)d_in[3 + 6 * L + 4];
        b3[L]           = (const float*)d_in[3 + 6 * L + 5];
    }
    wp.p[9]  = (const float*)d_in[21];
    const float* fc0b = (const float*)d_in[22];
    wp.p[10] = (const float*)d_in[23];
    const float* fc1b = (const float*)d_in[24];
    const float* outw = (const float*)d_in[25];
    const float* outb = (const float*)d_in[26];

    float *agg, *agg2, *h, *pool, *cnt, *hd2;
    __nv_bfloat16 *wth, *wtl;
    cudaGetSymbolAddress((void**)&agg,  g_agg);
    cudaGetSymbolAddress((void**)&agg2, g_agg2);
    cudaGetSymbolAddress((void**)&h,    g_h);
    cudaGetSymbolAddress((void**)&pool, g_pool);
    cudaGetSymbolAddress((void**)&cnt,  g_cnt);
    cudaGetSymbolAddress((void**)&hd2,  g_hd2);
    cudaGetSymbolAddress((void**)&wth,  g_wth);
    cudaGetSymbolAddress((void**)&wtl,  g_wtl);

    auto woff = [](int s) -> size_t { return s == 0 ? 0 : (size_t)4096 + (size_t)(s - 1) * 16384; };

    cudaFuncSetAttribute(fused_mlp<FIN, 3, 1, 1>, cudaFuncAttributeMaxDynamicSharedMemorySize, SMEM_FUSED);
    cudaFuncSetAttribute(fused_mlp<Hh, 3, 1, 1>,  cudaFuncAttributeMaxDynamicSharedMemorySize, SMEM_FUSED);
    cudaFuncSetAttribute(fused_mlp<Hh, 3, 1, 2>,  cudaFuncAttributeMaxDynamicSharedMemorySize, SMEM_FUSED);
    cudaFuncSetAttribute(fused_mlp<Hh, 2, 0, 0>,  cudaFuncAttributeMaxDynamicSharedMemorySize, SMEM_FUSED);

    const int TB = 256;
    int ggrid = (Nn + 63) / 64;   // 2344
    int hgrid = (Gg + 63) / 64;   // 32

    prep_all<<<11 * 128, 128>>>(wp, wth, wtl);

    // ---- layer 0 (K0 = 32): small zero + scatter; MLP zeroes agg2 inline ----
    zero_k<<<(Nn * FIN / 4 + TB - 1) / TB, TB>>>((float4*)agg, Nn * FIN / 4);
    scatter_k<FIN><<<(Ee * (FIN / 4) + TB - 1) / TB, TB>>>(agg, x, ei);
    {
        FusedW fw;
        for (int s = 0; s < 3; s++) { fw.wh[s] = wth + woff(s); fw.wl[s] = wtl + woff(s); }
        fw.b[0] = b1[0]; fw.b[1] = b2[0]; fw.b[2] = b3[0];
        fused_mlp<FIN, 3, 1, 1><<<ggrid, 256, SMEM_FUSED>>>(agg, x, fw, h, agg2, nullptr, Nn);
    }

    // ---- layer 1: scatter into agg2 (pre-zeroed); MLP zeroes agg inline ----
    scatter_k<Hh><<<(Ee * (Hh / 4) + TB - 1) / TB, TB>>>(agg2, h, ei);
    {
        FusedW fw;
        for (int s = 0; s < 3; s++) { fw.wh[s] = wth + woff(3 + s); fw.wl[s] = wtl + woff(3 + s); }
        fw.b[0] = b1[1]; fw.b[1] = b2[1]; fw.b[2] = b3[1];
        fused_mlp<Hh, 3, 1, 1><<<ggrid, 256, SMEM_FUSED>>>(agg2, h, fw, h, agg, nullptr, Nn);
    }

    // ---- layer 2: scatter into agg (pre-zeroed); MLP zeroes pool + cnt inline ----
    scatter_k<Hh><<<(Ee * (Hh / 4) + TB - 1) / TB, TB>>>(agg, h, ei);
    {
        FusedW fw;
        for (int s = 0; s < 3; s++) { fw.wh[s] = wth + woff(6 + s); fw.wl[s] = wtl + woff(6 + s); }
        fw.b[0] = b1[2]; fw.b[1] = b2[2]; fw.b[2] = b3[2];
        fused_mlp<Hh, 3, 1, 2><<<ggrid, 256, SMEM_FUSED>>>(agg, h, fw, h, pool, cnt, Nn);
    }

    // ---- global mean pool (pool/cnt zeroed by layer-2 MLP) ----
    {
        int warps = (Nn + PR - 1) / PR;
        pool_k<<<(warps * 32 + TB - 1) / TB, TB>>>(h, batch, pool);
    }
    cnt_k<<<((Nn + 31) / 32 + TB - 1) / TB, TB>>>(batch, cnt);
    div_k<<<(Gg * Hh + TB - 1) / TB, TB>>>(pool, cnt);

    // ---- classifier head (fc0 + fc1 fused) ----
    {
        FusedW fw;
        fw.wh[0] = wth + woff(9);  fw.wl[0] = wtl + woff(9);
        fw.wh[1] = wth + woff(10); fw.wl[1] = wtl + woff(10);
        fw.wh[2] = nullptr;        fw.wl[2] = nullptr;
        fw.b[0] = fc0b; fw.b[1] = fc1b; fw.b[2] = nullptr;
        fused_mlp<Hh, 2, 0, 0><<<hgrid, 256, SMEM_FUSED>>>(pool, nullptr, fw, hd2, nullptr, nullptr, Gg);
    }
    out_k<<<(Gg + 127) / 128, 128>>>(hd2, outw, outb, (float*)d_out);
}

// round 9
// speedup vs baseline: 1.2269x; 1.1798x over previous
#include <cuda_runtime.h>
#include <cuda_bf16.h>
#include <cstdint>

#define Nn  150000
#define Ee  600000
#define FIN 32
#define Hh  128
#define Gg  2048
#define NB_SCAN 586   // ceil(Nn/256)

// ---------------- scratch (device globals) ----------------------------------
__device__ float g_agg [Nn * Hh];
__device__ float g_h  [Nn * Hh];
__device__ float g_pool[Gg * Hh];
__device__ float g_cnt [Gg];
__device__ float g_hd2 [Gg * Hh];
__device__ int   g_deg [Nn];        // also used as fill cursor
__device__ int   g_rowptr[Nn + 1];
__device__ int   g_col [Ee];
__device__ int   g_bsum[1024];
#define WTOT (4096 + 10 * 16384)
__device__ __align__(256) __nv_bfloat16 g_wth[WTOT];
__device__ __align__(256) __nv_bfloat16 g_wtl[WTOT];

// ---------------- helpers -----------------------------------------------------
__device__ __forceinline__ uint32_t smem_u32(const void* p) {
    uint32_t a;
    asm("{ .reg .u64 t; cvta.to.shared.u64 t, %1; cvt.u32.u64 %0, t; }" : "=r"(a) : "l"(p));
    return a;
}

__device__ __forceinline__ void ldsm4(uint32_t (&r)[4], uint32_t addr) {
    asm volatile("ldmatrix.sync.aligned.m8n8.x4.shared.b16 {%0,%1,%2,%3}, [%4];"
                 : "=r"(r[0]), "=r"(r[1]), "=r"(r[2]), "=r"(r[3]) : "r"(addr));
}

__device__ __forceinline__ void mma16816(float (&c)[4], const uint32_t (&a)[4],
                                         uint32_t b0, uint32_t b1) {
    asm volatile(
        "mma.sync.aligned.m16n8k16.row.col.f32.bf16.bf16.f32 "
        "{%0,%1,%2,%3},{%4,%5,%6,%7},{%8,%9},{%0,%1,%2,%3};"
        : "+f"(c[0]), "+f"(c[1]), "+f"(c[2]), "+f"(c[3])
        : "r"(a[0]), "r"(a[1]), "r"(a[2]), "r"(a[3]), "r"(b0), "r"(b1));
}

__device__ __forceinline__ void split2(float a, float b, uint32_t& hv, uint32_t& lv) {
    __nv_bfloat16 ha = __float2bfloat16(a), hb = __float2bfloat16(b);
    float la = a - __bfloat162float(ha), lb = b - __bfloat162float(hb);
    __nv_bfloat162 hp = __halves2bfloat162(ha, hb);
    __nv_bfloat162 lp = __floats2bfloat162_rn(la, lb);
    hv = *reinterpret_cast<uint32_t*>(&hp);
    lv = *reinterpret_cast<uint32_t*>(&lp);
}

__device__ __forceinline__ void red4(float* p, float4 v) {
    asm volatile("red.global.add.v4.f32 [%0], {%1, %2, %3, %4};"
                 :: "l"(p), "f"(v.x), "f"(v.y), "f"(v.z), "f"(v.w) : "memory");
}

// ---------------- smem layout (round-5 proven config) ---------------------------
#define PITCH 136
#define OFF_A_HI 0u
#define OFF_A_LO 17408u
#define OFF_B_HI 34816u
#define OFF_B_LO 69632u
#define SMEM_FUSED 104448

template<int Ks>
__device__ __forceinline__ void gemm_acc(uint32_t sb, float (&acc)[2][4][4],
                                         int lane, int warp_m, int warp_n) {
#pragma unroll
    for (int i = 0; i < 2; i++)
#pragma unroll
        for (int j = 0; j < 4; j++)
#pragma unroll
            for (int k = 0; k < 4; k++) acc[i][j][k] = 0.f;

    int a_r = lane & 15;
    int a_c = (lane & 16) ? 8 : 0;
    int b_r = (lane & 7) + ((lane & 16) ? 8 : 0);
    int b_c = (lane & 8) ? 8 : 0;

#pragma unroll
    for (int kk = 0; kk < Ks / 16; kk++) {
        uint32_t ah[2][4], al[2][4], bh[2][4], bl[2][4];
#pragma unroll
        for (int mt = 0; mt < 2; mt++) {
            uint32_t off = (uint32_t)(((warp_m * 32 + mt * 16 + a_r) * PITCH + kk * 16 + a_c) * 2);
            ldsm4(ah[mt], sb + OFF_A_HI + off);
            ldsm4(al[mt], sb + OFF_A_LO + off);
        }
#pragma unroll
        for (int p = 0; p < 2; p++) {
            uint32_t off = (uint32_t)(((warp_n * 32 + p * 16 + b_r) * PITCH + kk * 16 + b_c) * 2);
            ldsm4(bh[p], sb + OFF_B_HI + off);
            ldsm4(bl[p], sb + OFF_B_LO + off);
        }
#pragma unroll
        for (int mt = 0; mt < 2; mt++)
#pragma unroll
            for (int nt = 0; nt < 4; nt++) {
                int p = nt >> 1, q = (nt & 1) * 2;
                mma16816(acc[mt][nt], ah[mt], bh[p][q], bh[p][q + 1]);
                mma16816(acc[mt][nt], ah[mt], bl[p][q], bl[p][q + 1]);
                mma16816(acc[mt][nt], al[mt], bh[p][q], bh[p][q + 1]);
            }
    }
}

__device__ __forceinline__ void stage_to_smem(char* smem, float (&acc)[2][4][4],
                                              const float* __restrict__ bias,
                                              int lane, int warp_m, int warp_n) {
    int qrow = lane >> 2, qcol = (lane & 3) * 2;
#pragma unroll
    for (int mt = 0; mt < 2; mt++) {
        int r0 = warp_m * 32 + mt * 16 + qrow;
#pragma unroll
        for (int nt = 0; nt < 4; nt++) {
            int col = warp_n * 32 + nt * 8 + qcol;
            float bs0 = __ldg(bias + col), bs1 = __ldg(bias + col + 1);
            float o0 = fmaxf(acc[mt][nt][0] + bs0, 0.f);
            float o1 = fmaxf(acc[mt][nt][1] + bs1, 0.f);
            float o2 = fmaxf(acc[mt][nt][2] + bs0, 0.f);
            float o3 = fmaxf(acc[mt][nt][3] + bs1, 0.f);
            uint32_t h0, l0, h1, l1;
            split2(o0, o1, h0, l0);
            split2(o2, o3, h1, l1);
            *reinterpret_cast<uint32_t*>(smem + OFF_A_HI + ((size_t)r0 * PITCH + col) * 2) = h0;
            *reinterpret_cast<uint32_t*>(smem + OFF_A_LO + ((size_t)r0 * PITCH + col) * 2) = l0;
            *reinterpret_cast<uint32_t*>(smem + OFF_A_HI + ((size_t)(r0 + 8) * PITCH + col) * 2) = h1;
            *reinterpret_cast<uint32_t*>(smem + OFF_A_LO + ((size_t)(r0 + 8) * PITCH + col) * 2) = l1;
        }
    }
}

template<int Kw>
__device__ __forceinline__ void load_w(char* smem, const __nv_bfloat16* __restrict__ wh,
                                       const __nv_bfloat16* __restrict__ wl, int tid) {
    constexpr int CH = Kw / 8;
    constexpr int ITER = 128 * CH / 256;
#pragma unroll
    for (int it = 0; it < ITER; it++) {
        int l = tid + it * 256;
        int row = l / CH, col = (l % CH) * 8;
        *reinterpret_cast<uint4*>(smem + OFF_B_HI + ((size_t)row * PITCH + col) * 2) =
            *reinterpret_cast<const uint4*>(wh + (size_t)row * Kw + col);
        *reinterpret_cast<uint4*>(smem + OFF_B_LO + ((size_t)row * PITCH + col) * 2) =
            *reinterpret_cast<const uint4*>(wl + (size_t)row * Kw + col);
    }
}

struct FusedW {
    const __nv_bfloat16* wh[3];
    const __nv_bfloat16* wl[3];
    const float* b[3];
};

// ---------------- fused MLP (round-5 shape) -------------------------------------
// IN: 0 = A fp32; 1 = A + A2 fp32.  ZPOOL: zero pool (Z) + cnt (Zc) inline.
template<int K0, int NST, int IN, int ZPOOL>
__global__ __launch_bounds__(256, 2)
void fused_mlp(const float* __restrict__ A, const float* __restrict__ A2,
               FusedW fw, float* __restrict__ C,
               float* __restrict__ Z, float* __restrict__ Zc, int M) {
    extern __shared__ char smem[];
    uint32_t sb = smem_u32(smem);
    int tid = threadIdx.x, lane = tid & 31, wid = tid >> 5;
    int warp_m = wid & 1, warp_n = wid >> 1;
    int m0 = blockIdx.x * 64;

    {
        constexpr int CH = K0 / 4;
        constexpr int ITER = 64 * CH / 256;
#pragma unroll
        for (int it = 0; it < ITER; it++) {
            int l = tid + it * 256;
            int row = l / CH, col = (l % CH) * 4;
            float4 v = make_float4(0.f, 0.f, 0.f, 0.f);
            int m = m0 + row;
            if (m < M) {
                v = *reinterpret_cast<const float4*>(A + (size_t)m * K0 + col);
                if (IN == 1) {
                    float4 w = *reinterpret_cast<const float4*>(A2 + (size_t)m * K0 + col);
                    v.x += w.x; v.y += w.y; v.z += w.z; v.w += w.w;
                }
            }
            uint32_t h0, l0, h1, l1;
            split2(v.x, v.y, h0, l0);
            split2(v.z, v.w, h1, l1);
            *reinterpret_cast<uint2*>(smem + OFF_A_HI + ((size_t)row * PITCH + col) * 2) = make_uint2(h0, h1);
            *reinterpret_cast<uint2*>(smem + OFF_A_LO + ((size_t)row * PITCH + col) * 2) = make_uint2(l0, l1);
        }
    }
    load_w<K0>(smem, fw.wh[0], fw.wl[0], tid);
    __syncthreads();

    if (ZPOOL) {
        const float4 z4 = make_float4(0.f, 0.f, 0.f, 0.f);
        if (blockIdx.x < 32) {                        // pool: 2048 rows = 32 blocks x 64 rows
#pragma unroll
            for (int it = 0; it < 8; it++) {
                int i = tid + it * 256;
                int row = (int)blockIdx.x * 64 + (i >> 5);
                reinterpret_cast<float4*>(Z + (size_t)row * 128)[i & 31] = z4;
            }
        } else if (blockIdx.x == 32) {                // cnt: 2048 floats = 512 float4
#pragma unroll
            for (int it = 0; it < 2; it++)
                reinterpret_cast<float4*>(Zc)[tid + it * 256] = z4;
        }
    }

    float acc[2][4][4];
    gemm_acc<K0>(sb, acc, lane, warp_m, warp_n);

#pragma unroll
    for (int s = 1; s < NST; s++) {
        __syncthreads();
        stage_to_smem(smem, acc, fw.b[s - 1], lane, warp_m, warp_n);
        load_w<128>(smem, fw.wh[s], fw.wl[s], tid);
        __syncthreads();
        gemm_acc<128>(sb, acc, lane, warp_m, warp_n);
    }

    const float* bias = fw.b[NST - 1];
    int qrow = lane >> 2, qcol = (lane & 3) * 2;
#pragma unroll
    for (int mt = 0; mt < 2; mt++) {
        int r0 = m0 + warp_m * 32 + mt * 16 + qrow;
        int r1 = r0 + 8;
#pragma unroll
        for (int nt = 0; nt < 4; nt++) {
            int col = warp_n * 32 + nt * 8 + qcol;
            float bs0 = __ldg(bias + col), bs1 = __ldg(bias + col + 1);
            float o0 = fmaxf(acc[mt][nt][0] + bs0, 0.f);
            float o1 = fmaxf(acc[mt][nt][1] + bs1, 0.f);
            float o2 = fmaxf(acc[mt][nt][2] + bs0, 0.f);
            float o3 = fmaxf(acc[mt][nt][3] + bs1, 0.f);
            if (r0 < M) *reinterpret_cast<float2*>(C + (size_t)r0 * 128 + col) = make_float2(o0, o1);
            if (r1 < M) *reinterpret_cast<float2*>(C + (size_t)r1 * 128 + col) = make_float2(o2, o3);
        }
    }
}

// ---------------- weight prep (11 slots, one launch) ---------------------------
struct WP { const float* p[11]; };

__global__ void prep_all(WP wp, __nv_bfloat16* __restrict__ hi, __nv_bfloat16* __restrict__ lo) {
    int slot = blockIdx.x >> 7;
    int n = blockIdx.x & 127;
    int K = (slot == 0) ? FIN : Hh;
    size_t off = (slot == 0) ? 0 : (size_t)4096 + (size_t)(slot - 1) * 16384;
    const float* W = wp.p[slot];
    for (int k = threadIdx.x; k < K; k += blockDim.x) {
        float v = W[k * Hh + n];
        __nv_bfloat16 h = __float2bfloat16(v);
        hi[off + (size_t)n * K + k] = h;
        lo[off + (size_t)n * K + k] = __float2bfloat16(v - __bfloat162float(h));
    }
}

// ---------------- CSR build -----------------------------------------------------
__global__ void deg_zero(int* deg) {
    int i = blockIdx.x * blockDim.x + threadIdx.x;
    if (i < Nn) deg[i] = 0;
}

__global__ void deg_k(const int* __restrict__ ei, int* __restrict__ deg) {
    int e = blockIdx.x * blockDim.x + threadIdx.x;
    if (e < Ee) atomicAdd(&deg[ei[Ee + e]], 1);
}

__global__ void scan1(const int* __restrict__ deg, int* __restrict__ bsum) {
    __shared__ int sm[256];
    int i = blockIdx.x * 256 + threadIdx.x;
    sm[threadIdx.x] = (i < Nn) ? deg[i] : 0;
    __syncthreads();
    for (int s = 128; s > 0; s >>= 1) {
        if (threadIdx.x < s) sm[threadIdx.x] += sm[threadIdx.x + s];
        __syncthreads();
    }
    if (threadIdx.x == 0) bsum[blockIdx.x] = sm[0];
}

__global__ void scan2(int* __restrict__ bsum) {
    __shared__ int sm[1024];
    int t = threadIdx.x;
    sm[t] = (t < NB_SCAN) ? bsum[t] : 0;
    __syncthreads();
    for (int s = 1; s < 1024; s <<= 1) {
        int v = (t >= s) ? sm[t - s] : 0;
        __syncthreads();
        sm[t] += v;
        __syncthreads();
    }
    if (t < NB_SCAN) bsum[t] = sm[t] - ((t < NB_SCAN) ? 0 : 0) - ((t < NB_SCAN) ? (sm[t] - sm[t]) : 0),
                     bsum[t] = sm[t];  // inclusive; exclusive derived in scan3
}

__global__ void scan3(const int* __restrict__ deg, const int* __restrict__ bsum,
                      int* __restrict__ rowptr, int* __restrict__ cursor) {
    __shared__ int sm[256];
    int i = blockIdx.x * 256 + threadIdx.x;
    int v = (i < Nn) ? deg[i] : 0;
    sm[threadIdx.x] = v;
    __syncthreads();
    for (int s = 1; s < 256; s <<= 1) {
        int u = (threadIdx.x >= s) ? sm[threadIdx.x - s] : 0;
        __syncthreads();
        sm[threadIdx.x] += u;
        __syncthreads();
    }
    int excl = sm[threadIdx.x] - v;                       // block-local exclusive
    int base = (blockIdx.x > 0) ? bsum[blockIdx.x - 1] : 0; // bsum is inclusive per block
    if (i < Nn) {
        rowptr[i] = base + excl;
        cursor[i] = base + excl;
    }
    if (i == 0) rowptr[Nn] = Ee;
}

__global__ void fill_k(const int* __restrict__ ei, int* __restrict__ cursor,
                       int* __restrict__ col) {
    int e = blockIdx.x * blockDim.x + threadIdx.x;
    if (e >= Ee) return;
    int d = ei[Ee + e];
    int p = atomicAdd(&cursor[d], 1);
    col[p] = ei[e];
}

// ---------------- gather aggregation (CSR) ---------------------------------------
__global__ void gather0(float* __restrict__ agg, const float* __restrict__ x,
                        const int* __restrict__ rowptr, const int* __restrict__ col) {
    int t = blockIdx.x * blockDim.x + threadIdx.x;
    int node = t >> 3;                 // 8 threads per node (32 feats)
    if (node >= Nn) return;
    int c = (t & 7) * 4;
    int beg = rowptr[node], end = rowptr[node + 1];
    float4 acc = make_float4(0.f, 0.f, 0.f, 0.f);
    for (int j = beg; j < end; j++) {
        int s = col[j];
        float4 v = *reinterpret_cast<const float4*>(x + (size_t)s * FIN + c);
        acc.x += v.x; acc.y += v.y; acc.z += v.z; acc.w += v.w;
    }
    *reinterpret_cast<float4*>(agg + (size_t)node * FIN + c) = acc;
}

__global__ void gatherH(float* __restrict__ agg, const float* __restrict__ h,
                        const int* __restrict__ rowptr, const int* __restrict__ col) {
    int gw = (blockIdx.x * blockDim.x + threadIdx.x) >> 5;   // warp = node
    int lane = threadIdx.x & 31;
    if (gw >= Nn) return;
    int beg = rowptr[gw], end = rowptr[gw + 1];
    float4 acc = make_float4(0.f, 0.f, 0.f, 0.f);
    int j = beg;
    for (; j + 2 <= end; j += 2) {                 // 2-way to raise MLP
        int s0 = col[j], s1 = col[j + 1];
        float4 v0 = *reinterpret_cast<const float4*>(h + (size_t)s0 * Hh + lane * 4);
        float4 v1 = *reinterpret_cast<const float4*>(h + (size_t)s1 * Hh + lane * 4);
        acc.x += v0.x + v1.x; acc.y += v0.y + v1.y;
        acc.z += v0.z + v1.z; acc.w += v0.w + v1.w;
    }
    if (j < end) {
        int s = col[j];
        float4 v = *reinterpret_cast<const float4*>(h + (size_t)s * Hh + lane * 4);
        acc.x += v.x; acc.y += v.y; acc.z += v.z; acc.w += v.w;
    }
    *reinterpret_cast<float4*>(agg + (size_t)gw * Hh + lane * 4) = acc;
}

// ---------------- pooling / head --------------------------------------------------
#define PR 16
__global__ void pool_k(const float* __restrict__ h, const int* __restrict__ batch,
                       float* __restrict__ pool) {
    int gw = (blockIdx.x * blockDim.x + threadIdx.x) >> 5;
    int lane = threadIdx.x & 31;
    const int NB = (Nn + PR - 1) / PR;
    if (gw >= NB) return;
    int n0 = gw * PR;
    int n1 = n0 + PR < Nn ? n0 + PR : Nn;
    float4 acc = make_float4(0.f, 0.f, 0.f, 0.f);
    int cur = batch[n0];
    for (int n = n0; n < n1; n++) {
        int g = batch[n];
        if (g != cur) {
            red4(&pool[(size_t)cur * Hh + lane * 4], acc);
            acc = make_float4(0.f, 0.f, 0.f, 0.f);
            cur = g;
        }
        float4 v = *reinterpret_cast<const float4*>(h + (size_t)n * Hh + lane * 4);
        acc.x += v.x; acc.y += v.y; acc.z += v.z; acc.w += v.w;
    }
    red4(&pool[(size_t)cur * Hh + lane * 4], acc);
}

__global__ void cnt_k(const int* __restrict__ batch, float* __restrict__ cnt) {
    int t = blockIdx.x * blockDim.x + threadIdx.x;
    const int R = 32;
    int n0 = t * R;
    if (n0 >= Nn) return;
    int n1 = n0 + R < Nn ? n0 + R : Nn;
    float acc = 0.f;
    int cur = batch[n0];
    for (int n = n0; n < n1; n++) {
        int g = batch[n];
        if (g != cur) { atomicAdd(&cnt[cur], acc); acc = 0.f; cur = g; }
        acc += 1.f;
    }
    atomicAdd(&cnt[cur], acc);
}

__global__ void div_k(float* __restrict__ pool, const float* __restrict__ cnt) {
    int idx = blockIdx.x * blockDim.x + threadIdx.x;
    if (idx >= Gg * Hh) return;
    pool[idx] *= 1.f / fmaxf(cnt[idx >> 7], 1.f);
}

__global__ void out_k(const float* __restrict__ g2, const float* __restrict__ ow,
                      const float* __restrict__ ob, float* __restrict__ out) {
    int g = blockIdx.x * blockDim.x + threadIdx.x;
    if (g >= Gg) return;
    float s0 = ob[0], s1 = ob[1];
#pragma unroll 4
    for (int k = 0; k < Hh; k++) {
        float v = g2[g * Hh + k];
        s0 += v * ow[k * 2 + 0];
        s1 += v * ow[k * 2 + 1];
    }
    out[g * 2 + 0] = s0;
    out[g * 2 + 1] = s1;
}

// ---------------- launch ----------------------------------------------------------
extern "C" void kernel_launch(void* const* d_in, const int* in_sizes, int n_in,
                              void* d_out, int out_size) {
    const float* x     = (const float*)d_in[0];
    const int*   ei    = (const int*)  d_in[1];
    const int*   batch = (const int*)  d_in[2];
    const float* b1[3], *b2[3], *b3[3];
    WP wp;
    for (int L = 0; L < 3; L++) {
        wp.p[3 * L + 0] = (const float*)d_in[3 + 6 * L + 0];
        b1[L]           = (const float*)d_in[3 + 6 * L + 1];
        wp.p[3 * L + 1] = (const float*)d_in[3 + 6 * L + 2];
        b2[L]           = (const float*)d_in[3 + 6 * L + 3];
        wp.p[3 * L + 2] = (const float*)d_in[3 + 6 * L + 4];
        b3[L]           = (const float*)d_in[3 + 6 * L + 5];
    }
    wp.p[9]  = (const float*)d_in[21];
    const float* fc0b = (const float*)d_in[22];
    wp.p[10] = (const float*)d_in[23];
    const float* fc1b = (const float*)d_in[24];
    const float* outw = (const float*)d_in[25];
    const float* outb = (const float*)d_in[26];

    float *agg, *h, *pool, *cnt, *hd2;
    int *deg, *rowptr, *colv, *bsum;
    __nv_bfloat16 *wth, *wtl;
    cudaGetSymbolAddress((void**)&agg,    g_agg);
    cudaGetSymbolAddress((void**)&h,      g_h);
    cudaGetSymbolAddress((void**)&pool,   g_pool);
    cudaGetSymbolAddress((void**)&cnt,    g_cnt);
    cudaGetSymbolAddress((void**)&hd2,    g_hd2);
    cudaGetSymbolAddress((void**)&deg,    g_deg);
    cudaGetSymbolAddress((void**)&rowptr, g_rowptr);
    cudaGetSymbolAddress((void**)&colv,   g_col);
    cudaGetSymbolAddress((void**)&bsum,   g_bsum);
    cudaGetSymbolAddress((void**)&wth,    g_wth);
    cudaGetSymbolAddress((void**)&wtl,    g_wtl);

    auto woff = [](int s) -> size_t { return s == 0 ? 0 : (size_t)4096 + (size_t)(s - 1) * 16384; };

    cudaFuncSetAttribute(fused_mlp<FIN, 3, 1, 0>, cudaFuncAttributeMaxDynamicSharedMemorySize, SMEM_FUSED);
    cudaFuncSetAttribute(fused_mlp<Hh, 3, 1, 0>,  cudaFuncAttributeMaxDynamicSharedMemorySize, SMEM_FUSED);
    cudaFuncSetAttribute(fused_mlp<Hh, 3, 1, 1>,  cudaFuncAttributeMaxDynamicSharedMemorySize, SMEM_FUSED);
    cudaFuncSetAttribute(fused_mlp<Hh, 2, 0, 0>,  cudaFuncAttributeMaxDynamicSharedMemorySize, SMEM_FUSED);

    const int TB = 256;
    int ggrid = (Nn + 63) / 64;   // 2344
    int hgrid = (Gg + 63) / 64;   // 32

    // ---- weight prep + CSR build (CSR reused by all 3 layers) ----
    prep_all<<<11 * 128, 128>>>(wp, wth, wtl);
    deg_zero<<<(Nn + TB - 1) / TB, TB>>>(deg);
    deg_k<<<(Ee + TB - 1) / TB, TB>>>(ei, deg);
    scan1<<<NB_SCAN, 256>>>(deg, bsum);
    scan2<<<1, 1024>>>(bsum);
    scan3<<<NB_SCAN, 256>>>(deg, bsum, rowptr, deg /* cursor reuses deg */);
    fill_k<<<(Ee + TB - 1) / TB, TB>>>(ei, deg, colv);

    // ---- layer 0 (K0 = 32) ----
    gather0<<<(Nn * 8 + TB - 1) / TB, TB>>>(agg, x, rowptr, colv);
    {
        FusedW fw;
        for (int s = 0; s < 3; s++) { fw.wh[s] = wth + woff(s); fw.wl[s] = wtl + woff(s); }
        fw.b[0] = b1[0]; fw.b[1] = b2[0]; fw.b[2] = b3[0];
        fused_mlp<FIN, 3, 1, 0><<<ggrid, 256, SMEM_FUSED>>>(agg, x, fw, h, nullptr, nullptr, Nn);
    }

    // ---- layer 1 ----
    gatherH<<<(Nn * 32 + TB - 1) / TB, TB>>>(agg, h, rowptr, colv);
    {
        FusedW fw;
        for (int s = 0; s < 3; s++) { fw.wh[s] = wth + woff(3 + s); fw.wl[s] = wtl + woff(3 + s); }
        fw.b[0] = b1[1]; fw.b[1] = b2[1]; fw.b[2] = b3[1];
        fused_mlp<Hh, 3, 1, 0><<<ggrid, 256, SMEM_FUSED>>>(agg, h, fw, h, nullptr, nullptr, Nn);
    }

    // ---- layer 2 (zeroes pool + cnt inline) ----
    gatherH<<<(Nn * 32 + TB - 1) / TB, TB>>>(agg, h, rowptr, colv);
    {
        FusedW fw;
        for (int s = 0; s < 3; s++) { fw.wh[s] = wth + woff(6 + s); fw.wl[s] = wtl + woff(6 + s); }
        fw.b[0] = b1[2]; fw.b[1] = b2[2]; fw.b[2] = b3[2];
        fused_mlp<Hh, 3, 1, 1><<<ggrid, 256, SMEM_FUSED>>>(agg, h, fw, h, pool, cnt, Nn);
    }

    // ---- global mean pool ----
    {
        int warps = (Nn + PR - 1) / PR;
        pool_k<<<(warps * 32 + TB - 1) / TB, TB>>>(h, batch, pool);
    }
    cnt_k<<<((Nn + 31) / 32 + TB - 1) / TB, TB>>>(batch, cnt);
    div_k<<<(Gg * Hh + TB - 1) / TB, TB>>>(pool, cnt);

    // ---- classifier head (fc0 + fc1 fused) ----
    {
        FusedW fw;
        fw.wh[0] = wth + woff(9);  fw.wl[0] = wtl + woff(9);
        fw.wh[1] = wth + woff(10); fw.wl[1] = wtl + woff(10);
        fw.wh[2] = nullptr;        fw.wl[2] = nullptr;
        fw.b[0] = fc0b; fw.b[1] = fc1b; fw.b[2] = nullptr;
        fused_mlp<Hh, 2, 0, 0><<<hgrid, 256, SMEM_FUSED>>>(pool, nullptr, fw, hd2, nullptr, nullptr, Gg);
    }
    out_k<<<(Gg + 127) / 128, 128>>>(hd2, outw, outb, (float*)d_out);
}

// round 10
// speedup vs baseline: 1.2412x; 1.0116x over previous
#include <cuda_runtime.h>
#include <cuda_bf16.h>
#include <cstdint>

#define Nn  150000
#define Ee  600000
#define FIN 32
#define Hh  128
#define Gg  2048
#define NB_SCAN 586   // ceil(Nn/256)

// ---------------- scratch (device globals) ----------------------------------
__device__ float g_hA [Nn * Hh];
__device__ float g_hB [Nn * Hh];
__device__ float g_pool[Gg * Hh];
__device__ float g_cnt [Gg];
__device__ float g_hd2 [Gg * Hh];
__device__ int   g_deg [Nn];        // also used as fill cursor
__device__ int   g_rowptr[Nn + 1];
__device__ int   g_col [Ee];
__device__ int   g_bsum[1024];
#define WTOT (4096 + 10 * 16384)
__device__ __align__(256) __nv_bfloat16 g_wth[WTOT];
__device__ __align__(256) __nv_bfloat16 g_wtl[WTOT];

// ---------------- helpers -----------------------------------------------------
__device__ __forceinline__ uint32_t smem_u32(const void* p) {
    uint32_t a;
    asm("{ .reg .u64 t; cvta.to.shared.u64 t, %1; cvt.u32.u64 %0, t; }" : "=r"(a) : "l"(p));
    return a;
}

__device__ __forceinline__ void ldsm4(uint32_t (&r)[4], uint32_t addr) {
    asm volatile("ldmatrix.sync.aligned.m8n8.x4.shared.b16 {%0,%1,%2,%3}, [%4];"
                 : "=r"(r[0]), "=r"(r[1]), "=r"(r[2]), "=r"(r[3]) : "r"(addr));
}

__device__ __forceinline__ void mma16816(float (&c)[4], const uint32_t (&a)[4],
                                         uint32_t b0, uint32_t b1) {
    asm volatile(
        "mma.sync.aligned.m16n8k16.row.col.f32.bf16.bf16.f32 "
        "{%0,%1,%2,%3},{%4,%5,%6,%7},{%8,%9},{%0,%1,%2,%3};"
        : "+f"(c[0]), "+f"(c[1]), "+f"(c[2]), "+f"(c[3])
        : "r"(a[0]), "r"(a[1]), "r"(a[2]), "r"(a[3]), "r"(b0), "r"(b1));
}

__device__ __forceinline__ void split2(float a, float b, uint32_t& hv, uint32_t& lv) {
    __nv_bfloat16 ha = __float2bfloat16(a), hb = __float2bfloat16(b);
    float la = a - __bfloat162float(ha), lb = b - __bfloat162float(hb);
    __nv_bfloat162 hp = __halves2bfloat162(ha, hb);
    __nv_bfloat162 lp = __floats2bfloat162_rn(la, lb);
    hv = *reinterpret_cast<uint32_t*>(&hp);
    lv = *reinterpret_cast<uint32_t*>(&lp);
}

__device__ __forceinline__ void red4(float* p, float4 v) {
    asm volatile("red.global.add.v4.f32 [%0], {%1, %2, %3, %4};"
                 :: "l"(p), "f"(v.x), "f"(v.y), "f"(v.z), "f"(v.w) : "memory");
}

// ---------------- smem layout (round-5 proven config) ---------------------------
#define PITCH 136
#define OFF_A_HI 0u
#define OFF_A_LO 17408u
#define OFF_B_HI 34816u
#define OFF_B_LO 69632u
#define SMEM_FUSED 104448

template<int Ks>
__device__ __forceinline__ void gemm_acc(uint32_t sb, float (&acc)[2][4][4],
                                         int lane, int warp_m, int warp_n) {
#pragma unroll
    for (int i = 0; i < 2; i++)
#pragma unroll
        for (int j = 0; j < 4; j++)
#pragma unroll
            for (int k = 0; k < 4; k++) acc[i][j][k] = 0.f;

    int a_r = lane & 15;
    int a_c = (lane & 16) ? 8 : 0;
    int b_r = (lane & 7) + ((lane & 16) ? 8 : 0);
    int b_c = (lane & 8) ? 8 : 0;

#pragma unroll
    for (int kk = 0; kk < Ks / 16; kk++) {
        uint32_t ah[2][4], al[2][4], bh[2][4], bl[2][4];
#pragma unroll
        for (int mt = 0; mt < 2; mt++) {
            uint32_t off = (uint32_t)(((warp_m * 32 + mt * 16 + a_r) * PITCH + kk * 16 + a_c) * 2);
            ldsm4(ah[mt], sb + OFF_A_HI + off);
            ldsm4(al[mt], sb + OFF_A_LO + off);
        }
#pragma unroll
        for (int p = 0; p < 2; p++) {
            uint32_t off = (uint32_t)(((warp_n * 32 + p * 16 + b_r) * PITCH + kk * 16 + b_c) * 2);
            ldsm4(bh[p], sb + OFF_B_HI + off);
            ldsm4(bl[p], sb + OFF_B_LO + off);
        }
#pragma unroll
        for (int mt = 0; mt < 2; mt++)
#pragma unroll
            for (int nt = 0; nt < 4; nt++) {
                int p = nt >> 1, q = (nt & 1) * 2;
                mma16816(acc[mt][nt], ah[mt], bh[p][q], bh[p][q + 1]);
                mma16816(acc[mt][nt], ah[mt], bl[p][q], bl[p][q + 1]);
                mma16816(acc[mt][nt], al[mt], bh[p][q], bh[p][q + 1]);
            }
    }
}

__device__ __forceinline__ void stage_to_smem(char* smem, float (&acc)[2][4][4],
                                              const float* __restrict__ bias,
                                              int lane, int warp_m, int warp_n) {
    int qrow = lane >> 2, qcol = (lane & 3) * 2;
#pragma unroll
    for (int mt = 0; mt < 2; mt++) {
        int r0 = warp_m * 32 + mt * 16 + qrow;
#pragma unroll
        for (int nt = 0; nt < 4; nt++) {
            int col = warp_n * 32 + nt * 8 + qcol;
            float bs0 = __ldg(bias + col), bs1 = __ldg(bias + col + 1);
            float o0 = fmaxf(acc[mt][nt][0] + bs0, 0.f);
            float o1 = fmaxf(acc[mt][nt][1] + bs1, 0.f);
            float o2 = fmaxf(acc[mt][nt][2] + bs0, 0.f);
            float o3 = fmaxf(acc[mt][nt][3] + bs1, 0.f);
            uint32_t h0, l0, h1, l1;
            split2(o0, o1, h0, l0);
            split2(o2, o3, h1, l1);
            *reinterpret_cast<uint32_t*>(smem + OFF_A_HI + ((size_t)r0 * PITCH + col) * 2) = h0;
            *reinterpret_cast<uint32_t*>(smem + OFF_A_LO + ((size_t)r0 * PITCH + col) * 2) = l0;
            *reinterpret_cast<uint32_t*>(smem + OFF_A_HI + ((size_t)(r0 + 8) * PITCH + col) * 2) = h1;
            *reinterpret_cast<uint32_t*>(smem + OFF_A_LO + ((size_t)(r0 + 8) * PITCH + col) * 2) = l1;
        }
    }
}

template<int Kw>
__device__ __forceinline__ void load_w(char* smem, const __nv_bfloat16* __restrict__ wh,
                                       const __nv_bfloat16* __restrict__ wl, int tid) {
    constexpr int CH = Kw / 8;
    constexpr int ITER = 128 * CH / 256;
#pragma unroll
    for (int it = 0; it < ITER; it++) {
        int l = tid + it * 256;
        int row = l / CH, col = (l % CH) * 8;
        *reinterpret_cast<uint4*>(smem + OFF_B_HI + ((size_t)row * PITCH + col) * 2) =
            *reinterpret_cast<const uint4*>(wh + (size_t)row * Kw + col);
        *reinterpret_cast<uint4*>(smem + OFF_B_LO + ((size_t)row * PITCH + col) * 2) =
            *reinterpret_cast<const uint4*>(wl + (size_t)row * Kw + col);
    }
}

struct FusedW {
    const __nv_bfloat16* wh[3];
    const __nv_bfloat16* wl[3];
    const float* b[3];
};

// ---------------- fused gather + MLP ---------------------------------------------
// GATHER: 0 = plain load of A rows; 1 = CSR gather(sum of A[col]) + self A[row].
// ZPOOL: zero pool (Z) + cnt (Zc) inline.
template<int K0, int NST, int GATHER, int ZPOOL>
__global__ __launch_bounds__(256, 2)
void fused_mlp(const float* __restrict__ A,
               const int* __restrict__ rowptr, const int* __restrict__ colv,
               FusedW fw, float* __restrict__ C,
               float* __restrict__ Z, float* __restrict__ Zc, int M) {
    extern __shared__ char smem[];
    uint32_t sb = smem_u32(smem);
    int tid = threadIdx.x, lane = tid & 31, wid = tid >> 5;
    int warp_m = wid & 1, warp_n = wid >> 1;
    int m0 = blockIdx.x * 64;

    // ---- stage A tile (64 x K0) ----
    if (GATHER == 0) {
        constexpr int CH = K0 / 4;
        constexpr int ITER = 64 * CH / 256;
#pragma unroll
        for (int it = 0; it < ITER; it++) {
            int l = tid + it * 256;
            int row = l / CH, col = (l % CH) * 4;
            float4 v = make_float4(0.f, 0.f, 0.f, 0.f);
            int m = m0 + row;
            if (m < M) v = *reinterpret_cast<const float4*>(A + (size_t)m * K0 + col);
            uint32_t h0, l0, h1, l1;
            split2(v.x, v.y, h0, l0);
            split2(v.z, v.w, h1, l1);
            *reinterpret_cast<uint2*>(smem + OFF_A_HI + ((size_t)row * PITCH + col) * 2) = make_uint2(h0, h1);
            *reinterpret_cast<uint2*>(smem + OFF_A_LO + ((size_t)row * PITCH + col) * 2) = make_uint2(l0, l1);
        }
    } else if (K0 == 128) {
        // warp = 8 consecutive rows; lane = 4-feature chunk
#pragma unroll
        for (int i = 0; i < 8; i++) {
            int lrow = wid * 8 + i;
            int row = m0 + lrow;
            float4 acc = make_float4(0.f, 0.f, 0.f, 0.f);
            if (row < M) {
                acc = *reinterpret_cast<const float4*>(A + (size_t)row * 128 + lane * 4);
                int beg = rowptr[row], end = rowptr[row + 1];
                for (int j = beg; j < end; j++) {
                    int s = colv[j];
                    float4 v = *reinterpret_cast<const float4*>(A + (size_t)s * 128 + lane * 4);
                    acc.x += v.x; acc.y += v.y; acc.z += v.z; acc.w += v.w;
                }
            }
            uint32_t h0, l0, h1, l1;
            split2(acc.x, acc.y, h0, l0);
            split2(acc.z, acc.w, h1, l1);
            *reinterpret_cast<uint2*>(smem + OFF_A_HI + ((size_t)lrow * PITCH + lane * 4) * 2) = make_uint2(h0, h1);
            *reinterpret_cast<uint2*>(smem + OFF_A_LO + ((size_t)lrow * PITCH + lane * 4) * 2) = make_uint2(l0, l1);
        }
    } else {
        // K0 == 32: warp covers 4 rows at a time (8 lanes x float4 per row)
        int sub = lane >> 3, c = (lane & 7) * 4;
#pragma unroll
        for (int i = 0; i < 2; i++) {
            int lrow = wid * 8 + i * 4 + sub;
            int row = m0 + lrow;
            float4 acc = make_float4(0.f, 0.f, 0.f, 0.f);
            if (row < M) {
                acc = *reinterpret_cast<const float4*>(A + (size_t)row * FIN + c);
                int beg = rowptr[row], end = rowptr[row + 1];
                for (int j = beg; j < end; j++) {
                    int s = colv[j];
                    float4 v = *reinterpret_cast<const float4*>(A + (size_t)s * FIN + c);
                    acc.x += v.x; acc.y += v.y; acc.z += v.z; acc.w += v.w;
                }
            }
            uint32_t h0, l0, h1, l1;
            split2(acc.x, acc.y, h0, l0);
            split2(acc.z, acc.w, h1, l1);
            *reinterpret_cast<uint2*>(smem + OFF_A_HI + ((size_t)lrow * PITCH + c) * 2) = make_uint2(h0, h1);
            *reinterpret_cast<uint2*>(smem + OFF_A_LO + ((size_t)lrow * PITCH + c) * 2) = make_uint2(l0, l1);
        }
    }
    load_w<K0>(smem, fw.wh[0], fw.wl[0], tid);
    __syncthreads();

    if (ZPOOL) {
        const float4 z4 = make_float4(0.f, 0.f, 0.f, 0.f);
        if (blockIdx.x < 32) {
#pragma unroll
            for (int it = 0; it < 8; it++) {
                int i = tid + it * 256;
                int row = (int)blockIdx.x * 64 + (i >> 5);
                reinterpret_cast<float4*>(Z + (size_t)row * 128)[i & 31] = z4;
            }
        } else if (blockIdx.x == 32) {
#pragma unroll
            for (int it = 0; it < 2; it++)
                reinterpret_cast<float4*>(Zc)[tid + it * 256] = z4;
        }
    }

    float acc[2][4][4];
    gemm_acc<K0>(sb, acc, lane, warp_m, warp_n);

#pragma unroll
    for (int s = 1; s < NST; s++) {
        __syncthreads();
        stage_to_smem(smem, acc, fw.b[s - 1], lane, warp_m, warp_n);
        load_w<128>(smem, fw.wh[s], fw.wl[s], tid);
        __syncthreads();
        gemm_acc<128>(sb, acc, lane, warp_m, warp_n);
    }

    const float* bias = fw.b[NST - 1];
    int qrow = lane >> 2, qcol = (lane & 3) * 2;
#pragma unroll
    for (int mt = 0; mt < 2; mt++) {
        int r0 = m0 + warp_m * 32 + mt * 16 + qrow;
        int r1 = r0 + 8;
#pragma unroll
        for (int nt = 0; nt < 4; nt++) {
            int col = warp_n * 32 + nt * 8 + qcol;
            float bs0 = __ldg(bias + col), bs1 = __ldg(bias + col + 1);
            float o0 = fmaxf(acc[mt][nt][0] + bs0, 0.f);
            float o1 = fmaxf(acc[mt][nt][1] + bs1, 0.f);
            float o2 = fmaxf(acc[mt][nt][2] + bs0, 0.f);
            float o3 = fmaxf(acc[mt][nt][3] + bs1, 0.f);
            if (r0 < M) *reinterpret_cast<float2*>(C + (size_t)r0 * 128 + col) = make_float2(o0, o1);
            if (r1 < M) *reinterpret_cast<float2*>(C + (size_t)r1 * 128 + col) = make_float2(o2, o3);
        }
    }
}

// ---------------- weight prep (11 slots, one launch) ---------------------------
struct WP { const float* p[11]; };

__global__ void prep_all(WP wp, __nv_bfloat16* __restrict__ hi, __nv_bfloat16* __restrict__ lo) {
    int slot = blockIdx.x >> 7;
    int n = blockIdx.x & 127;
    int K = (slot == 0) ? FIN : Hh;
    size_t off = (slot == 0) ? 0 : (size_t)4096 + (size_t)(slot - 1) * 16384;
    const float* W = wp.p[slot];
    for (int k = threadIdx.x; k < K; k += blockDim.x) {
        float v = W[k * Hh + n];
        __nv_bfloat16 h = __float2bfloat16(v);
        hi[off + (size_t)n * K + k] = h;
        lo[off + (size_t)n * K + k] = __float2bfloat16(v - __bfloat162float(h));
    }
}

// ---------------- CSR build -----------------------------------------------------
__global__ void deg_zero(int* deg) {
    int i = blockIdx.x * blockDim.x + threadIdx.x;
    if (i < Nn) deg[i] = 0;
}

__global__ void deg_k(const int* __restrict__ ei, int* __restrict__ deg) {
    int e = blockIdx.x * blockDim.x + threadIdx.x;
    if (e < Ee) atomicAdd(&deg[ei[Ee + e]], 1);
}

__global__ void scan1(const int* __restrict__ deg, int* __restrict__ bsum) {
    __shared__ int sm[256];
    int i = blockIdx.x * 256 + threadIdx.x;
    sm[threadIdx.x] = (i < Nn) ? deg[i] : 0;
    __syncthreads();
    for (int s = 128; s > 0; s >>= 1) {
        if (threadIdx.x < s) sm[threadIdx.x] += sm[threadIdx.x + s];
        __syncthreads();
    }
    if (threadIdx.x == 0) bsum[blockIdx.x] = sm[0];
}

__global__ void scan2(int* __restrict__ bsum) {
    __shared__ int sm[1024];
    int t = threadIdx.x;
    sm[t] = (t < NB_SCAN) ? bsum[t] : 0;
    __syncthreads();
    for (int s = 1; s < 1024; s <<= 1) {
        int v = (t >= s) ? sm[t - s] : 0;
        __syncthreads();
        sm[t] += v;
        __syncthreads();
    }
    if (t < NB_SCAN) bsum[t] = sm[t];   // inclusive per-block sums
}

__global__ void scan3(const int* __restrict__ deg, const int* __restrict__ bsum,
                      int* __restrict__ rowptr, int* __restrict__ cursor) {
    __shared__ int sm[256];
    int i = blockIdx.x * 256 + threadIdx.x;
    int v = (i < Nn) ? deg[i] : 0;
    sm[threadIdx.x] = v;
    __syncthreads();
    for (int s = 1; s < 256; s <<= 1) {
        int u = (threadIdx.x >= s) ? sm[threadIdx.x - s] : 0;
        __syncthreads();
        sm[threadIdx.x] += u;
        __syncthreads();
    }
    int excl = sm[threadIdx.x] - v;
    int base = (blockIdx.x > 0) ? bsum[blockIdx.x - 1] : 0;
    if (i < Nn) {
        rowptr[i] = base + excl;
        cursor[i] = base + excl;
    }
    if (i == 0) rowptr[Nn] = Ee;
}

__global__ void fill_k(const int* __restrict__ ei, int* __restrict__ cursor,
                       int* __restrict__ col) {
    int e = blockIdx.x * blockDim.x + threadIdx.x;
    if (e >= Ee) return;
    int d = ei[Ee + e];
    int p = atomicAdd(&cursor[d], 1);
    col[p] = ei[e];
}

// ---------------- pooling / head --------------------------------------------------
#define PR 16
__global__ void pool_k(const float* __restrict__ h, const int* __restrict__ batch,
                       float* __restrict__ pool) {
    int gw = (blockIdx.x * blockDim.x + threadIdx.x) >> 5;
    int lane = threadIdx.x & 31;
    const int NB = (Nn + PR - 1) / PR;
    if (gw >= NB) return;
    int n0 = gw * PR;
    int n1 = n0 + PR < Nn ? n0 + PR : Nn;
    float4 acc = make_float4(0.f, 0.f, 0.f, 0.f);
    int cur = batch[n0];
    for (int n = n0; n < n1; n++) {
        int g = batch[n];
        if (g != cur) {
            red4(&pool[(size_t)cur * Hh + lane * 4], acc);
            acc = make_float4(0.f, 0.f, 0.f, 0.f);
            cur = g;
        }
        float4 v = *reinterpret_cast<const float4*>(h + (size_t)n * Hh + lane * 4);
        acc.x += v.x; acc.y += v.y; acc.z += v.z; acc.w += v.w;
    }
    red4(&pool[(size_t)cur * Hh + lane * 4], acc);
}

__global__ void cnt_k(const int* __restrict__ batch, float* __restrict__ cnt) {
    int t = blockIdx.x * blockDim.x + threadIdx.x;
    const int R = 32;
    int n0 = t * R;
    if (n0 >= Nn) return;
    int n1 = n0 + R < Nn ? n0 + R : Nn;
    float acc = 0.f;
    int cur = batch[n0];
    for (int n = n0; n < n1; n++) {
        int g = batch[n];
        if (g != cur) { atomicAdd(&cnt[cur], acc); acc = 0.f; cur = g; }
        acc += 1.f;
    }
    atomicAdd(&cnt[cur], acc);
}

__global__ void div_k(float* __restrict__ pool, const float* __restrict__ cnt) {
    int idx = blockIdx.x * blockDim.x + threadIdx.x;
    if (idx >= Gg * Hh) return;
    pool[idx] *= 1.f / fmaxf(cnt[idx >> 7], 1.f);
}

__global__ void out_k(const float* __restrict__ g2, const float* __restrict__ ow,
                      const float* __restrict__ ob, float* __restrict__ out) {
    int g = blockIdx.x * blockDim.x + threadIdx.x;
    if (g >= Gg) return;
    float s0 = ob[0], s1 = ob[1];
#pragma unroll 4
    for (int k = 0; k < Hh; k++) {
        float v = g2[g * Hh + k];
        s0 += v * ow[k * 2 + 0];
        s1 += v * ow[k * 2 + 1];
    }
    out[g * 2 + 0] = s0;
    out[g * 2 + 1] = s1;
}

// ---------------- launch ----------------------------------------------------------
extern "C" void kernel_launch(void* const* d_in, const int* in_sizes, int n_in,
                              void* d_out, int out_size) {
    const float* x     = (const float*)d_in[0];
    const int*   ei    = (const int*)  d_in[1];
    const int*   batch = (const int*)  d_in[2];
    const float* b1[3], *b2[3], *b3[3];
    WP wp;
    for (int L = 0; L < 3; L++) {
        wp.p[3 * L + 0] = (const float*)d_in[3 + 6 * L + 0];
        b1[L]           = (const float*)d_in[3 + 6 * L + 1];
        wp.p[3 * L + 1] = (const float*)d_in[3 + 6 * L + 2];
        b2[L]           = (const float*)d_in[3 + 6 * L + 3];
        wp.p[3 * L + 2] = (const float*)d_in[3 + 6 * L + 4];
        b3[L]           = (const float*)d_in[3 + 6 * L + 5];
    }
    wp.p[9]  = (const float*)d_in[21];
    const float* fc0b = (const float*)d_in[22];
    wp.p[10] = (const float*)d_in[23];
    const float* fc1b = (const float*)d_in[24];
    const float* outw = (const float*)d_in[25];
    const float* outb = (const float*)d_in[26];

    float *hA, *hB, *pool, *cnt, *hd2;
    int *deg, *rowptr, *colv, *bsum;
    __nv_bfloat16 *wth, *wtl;
    cudaGetSymbolAddress((void**)&hA,     g_hA);
    cudaGetSymbolAddress((void**)&hB,     g_hB);
    cudaGetSymbolAddress((void**)&pool,   g_pool);
    cudaGetSymbolAddress((void**)&cnt,    g_cnt);
    cudaGetSymbolAddress((void**)&hd2,    g_hd2);
    cudaGetSymbolAddress((void**)&deg,    g_deg);
    cudaGetSymbolAddress((void**)&rowptr, g_rowptr);
    cudaGetSymbolAddress((void**)&colv,   g_col);
    cudaGetSymbolAddress((void**)&bsum,   g_bsum);
    cudaGetSymbolAddress((void**)&wth,    g_wth);
    cudaGetSymbolAddress((void**)&wtl,    g_wtl);

    auto woff = [](int s) -> size_t { return s == 0 ? 0 : (size_t)4096 + (size_t)(s - 1) * 16384; };

    cudaFuncSetAttribute(fused_mlp<FIN, 3, 1, 0>, cudaFuncAttributeMaxDynamicSharedMemorySize, SMEM_FUSED);
    cudaFuncSetAttribute(fused_mlp<Hh, 3, 1, 0>,  cudaFuncAttributeMaxDynamicSharedMemorySize, SMEM_FUSED);
    cudaFuncSetAttribute(fused_mlp<Hh, 3, 1, 1>,  cudaFuncAttributeMaxDynamicSharedMemorySize, SMEM_FUSED);
    cudaFuncSetAttribute(fused_mlp<Hh, 2, 0, 0>,  cudaFuncAttributeMaxDynamicSharedMemorySize, SMEM_FUSED);

    const int TB = 256;
    int ggrid = (Nn + 63) / 64;   // 2344
    int hgrid = (Gg + 63) / 64;   // 32

    // ---- weight prep + CSR build ----
    prep_all<<<11 * 128, 128>>>(wp, wth, wtl);
    deg_zero<<<(Nn + TB - 1) / TB, TB>>>(deg);
    deg_k<<<(Ee + TB - 1) / TB, TB>>>(ei, deg);
    scan1<<<NB_SCAN, 256>>>(deg, bsum);
    scan2<<<1, 1024>>>(bsum);
    scan3<<<NB_SCAN, 256>>>(deg, bsum, rowptr, deg);
    fill_k<<<(Ee + TB - 1) / TB, TB>>>(ei, deg, colv);

    // ---- layer 0: gather(x) + MLP -> hA ----
    {
        FusedW fw;
        for (int s = 0; s < 3; s++) { fw.wh[s] = wth + woff(s); fw.wl[s] = wtl + woff(s); }
        fw.b[0] = b1[0]; fw.b[1] = b2[0]; fw.b[2] = b3[0];
        fused_mlp<FIN, 3, 1, 0><<<ggrid, 256, SMEM_FUSED>>>(x, rowptr, colv, fw, hA, nullptr, nullptr, Nn);
    }
    // ---- layer 1: gather(hA) + MLP -> hB ----
    {
        FusedW fw;
        for (int s = 0; s < 3; s++) { fw.wh[s] = wth + woff(3 + s); fw.wl[s] = wtl + woff(3 + s); }
        fw.b[0] = b1[1]; fw.b[1] = b2[1]; fw.b[2] = b3[1];
        fused_mlp<Hh, 3, 1, 0><<<ggrid, 256, SMEM_FUSED>>>(hA, rowptr, colv, fw, hB, nullptr, nullptr, Nn);
    }
    // ---- layer 2: gather(hB) + MLP -> hA (zeroes pool + cnt inline) ----
    {
        FusedW fw;
        for (int s = 0; s < 3; s++) { fw.wh[s] = wth + woff(6 + s); fw.wl[s] = wtl + woff(6 + s); }
        fw.b[0] = b1[2]; fw.b[1] = b2[2]; fw.b[2] = b3[2];
        fused_mlp<Hh, 3, 1, 1><<<ggrid, 256, SMEM_FUSED>>>(hB, rowptr, colv, fw, hA, pool, cnt, Nn);
    }

    // ---- global mean pool ----
    {
        int warps = (Nn + PR - 1) / PR;
        pool_k<<<(warps * 32 + TB - 1) / TB, TB>>>(hA, batch, pool);
    }
    cnt_k<<<((Nn + 31) / 32 + TB - 1) / TB, TB>>>(batch, cnt);
    div_k<<<(Gg * Hh + TB - 1) / TB, TB>>>(pool, cnt);

    // ---- classifier head (fc0 + fc1 fused) ----
    {
        FusedW fw;
        fw.wh[0] = wth + woff(9);  fw.wl[0] = wtl + woff(9);
        fw.wh[1] = wth + woff(10); fw.wl[1] = wtl + woff(10);
        fw.wh[2] = nullptr;        fw.wl[2] = nullptr;
        fw.b[0] = fc0b; fw.b[1] = fc1b; fw.b[2] = nullptr;
        fused_mlp<Hh, 2, 0, 0><<<hgrid, 256, SMEM_FUSED>>>(pool, nullptr, nullptr, fw, hd2, nullptr, nullptr, Gg);
    }
    out_k<<<(Gg + 127) / 128, 128>>>(hd2, outw, outb, (float*)d_out);
}